// round 1
// baseline (speedup 1.0000x reference)
#include <cuda_runtime.h>
#include <math.h>

// Problem constants
#define BB    4
#define NN    1024
#define DD    512
#define HH    8
#define HDIM  64
#define EE    4
#define LL    3
#define MTOT  (BB*NN)   // 4096

// Scratch: h, q, k, v, att  (5 * 4096 * 512 floats = 42 MB)
__device__ float g_scratch[5ull * MTOT * DD];

// ---------------------------------------------------------------------------
// GEMM: C[M,Nn] = A[M,K] @ W[K,Nn] + bias (+ resid). 64x64 tile, 4x4/thread.
// ---------------------------------------------------------------------------
__global__ __launch_bounds__(256) void gemm_bias_kernel(
    const float* __restrict__ A, const float* __restrict__ W,
    const float* __restrict__ bias, const float* __restrict__ resid,
    float* __restrict__ C, int K, int Nn)
{
    __shared__ float As[16][68];   // k-major, padded
    __shared__ float Bs[16][64];   // k-major
    const int tid = threadIdx.x;
    const int ty = tid >> 4, tx = tid & 15;
    const int m0 = blockIdx.y << 6, n0 = blockIdx.x << 6;
    const int lm = tid >> 2;            // 0..63  (A row)
    const int lk = (tid & 3) << 2;      // 0,4,8,12
    const int wk = tid >> 4;            // 0..15  (W row)
    const int wn = (tid & 15) << 2;     // 0..60

    const float* Ab = A + (size_t)m0 * K;
    const float* Wb = W + n0;
    float acc[4][4] = {};

    for (int k0 = 0; k0 < K; k0 += 16) {
        float4 av = *(const float4*)(Ab + (size_t)lm * K + k0 + lk);
        float4 bv = *(const float4*)(Wb + (size_t)(k0 + wk) * Nn + wn);
        As[lk + 0][lm] = av.x; As[lk + 1][lm] = av.y;
        As[lk + 2][lm] = av.z; As[lk + 3][lm] = av.w;
        *(float4*)&Bs[wk][wn] = bv;
        __syncthreads();
#pragma unroll
        for (int kk = 0; kk < 16; kk++) {
            float4 a = *(const float4*)&As[kk][ty << 2];
            float4 b = *(const float4*)&Bs[kk][tx << 2];
            acc[0][0] += a.x * b.x; acc[0][1] += a.x * b.y;
            acc[0][2] += a.x * b.z; acc[0][3] += a.x * b.w;
            acc[1][0] += a.y * b.x; acc[1][1] += a.y * b.y;
            acc[1][2] += a.y * b.z; acc[1][3] += a.y * b.w;
            acc[2][0] += a.z * b.x; acc[2][1] += a.z * b.y;
            acc[2][2] += a.z * b.z; acc[2][3] += a.z * b.w;
            acc[3][0] += a.w * b.x; acc[3][1] += a.w * b.y;
            acc[3][2] += a.w * b.z; acc[3][3] += a.w * b.w;
        }
        __syncthreads();
    }

    float4 bb = *(const float4*)(bias + n0 + (tx << 2));
#pragma unroll
    for (int r = 0; r < 4; r++) {
        int m = m0 + (ty << 2) + r;
        float4 o;
        o.x = acc[r][0] + bb.x; o.y = acc[r][1] + bb.y;
        o.z = acc[r][2] + bb.z; o.w = acc[r][3] + bb.w;
        if (resid) {
            float4 rv = *(const float4*)(resid + (size_t)m * Nn + n0 + (tx << 2));
            o.x += rv.x; o.y += rv.y; o.z += rv.z; o.w += rv.w;
        }
        *(float4*)(C + (size_t)m * Nn + n0 + (tx << 2)) = o;
    }
}

// ---------------------------------------------------------------------------
// Flash attention per (b, h, 64-row i-tile): S = QK^T/8 + edges@ew, online
// softmax, O = P@V, O /= l.  q/k/v layout: [B*N, D] with head h at cols h*64.
// Dynamic smem: Qs[64][64] d-major | Ks[64][64] d-major | Vs[64][64] | Ps[64][65]
// ---------------------------------------------------------------------------
__global__ __launch_bounds__(256) void attn_kernel(
    const float* __restrict__ q, const float* __restrict__ k,
    const float* __restrict__ v, const float* __restrict__ edges,
    const float* __restrict__ ewl, float* __restrict__ out)
{
    extern __shared__ float sm[];
    float* Qs = sm;              // [d*64 + i]
    float* Ks = sm + 4096;       // [d*64 + j]
    float* Vs = sm + 8192;       // [j*64 + d]
    float* Ps = sm + 12288;      // [j*65 + i]

    const int h = blockIdx.x, it = blockIdx.y, b = blockIdx.z;
    const int i0 = it << 6;
    const int tid = threadIdx.x;
    const int ty = tid >> 4, tx = tid & 15;
    const int li = tid >> 2;            // 0..63
    const int lc = (tid & 3) << 4;      // 0,16,32,48

    const float ew0 = ewl[0 * HH + h], ew1 = ewl[1 * HH + h];
    const float ew2 = ewl[2 * HH + h], ew3 = ewl[3 * HH + h];

    // Load Q tile (transposed into d-major smem)
    const float* qb = q + ((size_t)(b * NN + i0)) * DD + h * HDIM;
#pragma unroll
    for (int c = 0; c < 4; c++) {
        float4 t = *(const float4*)(qb + (size_t)li * DD + lc + (c << 2));
        int d = lc + (c << 2);
        Qs[(d + 0) * 64 + li] = t.x; Qs[(d + 1) * 64 + li] = t.y;
        Qs[(d + 2) * 64 + li] = t.z; Qs[(d + 3) * 64 + li] = t.w;
    }

    float mrow[4] = {-1e30f, -1e30f, -1e30f, -1e30f};
    float lrow[4] = {0.f, 0.f, 0.f, 0.f};
    float O[4][4] = {};

    const float* kb0 = k + ((size_t)(b * NN)) * DD + h * HDIM;
    const float* vb0 = v + ((size_t)(b * NN)) * DD + h * HDIM;

    for (int j0 = 0; j0 < NN; j0 += 64) {
        __syncthreads();   // protect Vs/Ps from previous tile (and Q first time)
        // Load K (transposed d-major) and V (row-major)
#pragma unroll
        for (int c = 0; c < 4; c++) {
            int d = lc + (c << 2);
            float4 t = *(const float4*)(kb0 + (size_t)(j0 + li) * DD + d);
            Ks[(d + 0) * 64 + li] = t.x; Ks[(d + 1) * 64 + li] = t.y;
            Ks[(d + 2) * 64 + li] = t.z; Ks[(d + 3) * 64 + li] = t.w;
            float4 tv = *(const float4*)(vb0 + (size_t)(j0 + li) * DD + d);
            *(float4*)&Vs[li * 64 + d] = tv;
        }
        __syncthreads();

        // S = Q @ K^T
        float s[4][4] = {};
#pragma unroll 8
        for (int kk = 0; kk < 64; kk++) {
            float4 a = *(const float4*)&Qs[kk * 64 + (ty << 2)];
            float4 bv = *(const float4*)&Ks[kk * 64 + (tx << 2)];
            s[0][0] += a.x * bv.x; s[0][1] += a.x * bv.y;
            s[0][2] += a.x * bv.z; s[0][3] += a.x * bv.w;
            s[1][0] += a.y * bv.x; s[1][1] += a.y * bv.y;
            s[1][2] += a.y * bv.z; s[1][3] += a.y * bv.w;
            s[2][0] += a.z * bv.x; s[2][1] += a.z * bv.y;
            s[2][2] += a.z * bv.z; s[2][3] += a.z * bv.w;
            s[3][0] += a.w * bv.x; s[3][1] += a.w * bv.y;
            s[3][2] += a.w * bv.z; s[3][3] += a.w * bv.w;
        }

        // Scale + edge bias (eb[h] is constant over j -> cancels in softmax)
        const float* ebase = edges +
            (((size_t)b * NN + i0 + (ty << 2)) * NN + j0 + (tx << 2)) * EE;
#pragma unroll
        for (int r = 0; r < 4; r++) {
#pragma unroll
            for (int c = 0; c < 4; c++) {
                float4 ev = *(const float4*)(ebase + ((size_t)r * NN + c) * EE);
                s[r][c] = s[r][c] * 0.125f +
                          ev.x * ew0 + ev.y * ew1 + ev.z * ew2 + ev.w * ew3;
            }
        }

        // Online softmax update
#pragma unroll
        for (int r = 0; r < 4; r++) {
            float mt = fmaxf(fmaxf(s[r][0], s[r][1]), fmaxf(s[r][2], s[r][3]));
#pragma unroll
            for (int off = 1; off < 16; off <<= 1)
                mt = fmaxf(mt, __shfl_xor_sync(0xffffffffu, mt, off, 16));
            float mn = fmaxf(mrow[r], mt);
            float f = __expf(mrow[r] - mn);
            mrow[r] = mn;
            float rs = 0.f;
#pragma unroll
            for (int c = 0; c < 4; c++) {
                float p = __expf(s[r][c] - mn);
                s[r][c] = p;
                rs += p;
            }
#pragma unroll
            for (int off = 1; off < 16; off <<= 1)
                rs += __shfl_xor_sync(0xffffffffu, rs, off, 16);
            lrow[r] = lrow[r] * f + rs;
            O[r][0] *= f; O[r][1] *= f; O[r][2] *= f; O[r][3] *= f;
        }

        // Stash P (j-major, padded rows)
#pragma unroll
        for (int r = 0; r < 4; r++)
#pragma unroll
            for (int c = 0; c < 4; c++)
                Ps[((tx << 2) + c) * 65 + (ty << 2) + r] = s[r][c];
        __syncthreads();

        // O += P @ V
#pragma unroll 8
        for (int j = 0; j < 64; j++) {
            float p0 = Ps[j * 65 + (ty << 2) + 0];
            float p1 = Ps[j * 65 + (ty << 2) + 1];
            float p2 = Ps[j * 65 + (ty << 2) + 2];
            float p3 = Ps[j * 65 + (ty << 2) + 3];
            float4 vv = *(const float4*)&Vs[j * 64 + (tx << 2)];
            O[0][0] += p0 * vv.x; O[0][1] += p0 * vv.y;
            O[0][2] += p0 * vv.z; O[0][3] += p0 * vv.w;
            O[1][0] += p1 * vv.x; O[1][1] += p1 * vv.y;
            O[1][2] += p1 * vv.z; O[1][3] += p1 * vv.w;
            O[2][0] += p2 * vv.x; O[2][1] += p2 * vv.y;
            O[2][2] += p2 * vv.z; O[2][3] += p2 * vv.w;
            O[3][0] += p3 * vv.x; O[3][1] += p3 * vv.y;
            O[3][2] += p3 * vv.z; O[3][3] += p3 * vv.w;
        }
    }

    // Normalize and write out
    float* obase = out + ((size_t)(b * NN + i0)) * DD + h * HDIM;
#pragma unroll
    for (int r = 0; r < 4; r++) {
        float inv = 1.0f / lrow[r];
        float4 o;
        o.x = O[r][0] * inv; o.y = O[r][1] * inv;
        o.z = O[r][2] * inv; o.w = O[r][3] * inv;
        *(float4*)(obase + (size_t)((ty << 2) + r) * DD + (tx << 2)) = o;
    }
}

// ---------------------------------------------------------------------------
// Row LayerNorm: 4096 rows x 512 cols, 128 threads/row (4 floats each).
// ---------------------------------------------------------------------------
__device__ __forceinline__ float warp_sum(float s) {
#pragma unroll
    for (int o = 16; o; o >>= 1) s += __shfl_xor_sync(0xffffffffu, s, o);
    return s;
}

__global__ __launch_bounds__(128) void ln_kernel(
    const float* __restrict__ hin, const float* __restrict__ gw,
    const float* __restrict__ gb, float* __restrict__ out)
{
    __shared__ float red[4];
    const int row = blockIdx.x;
    const int tid = threadIdx.x;
    const int wid = tid >> 5, lane = tid & 31;
    const float* hr = hin + (size_t)row * DD;

    float4 x = *(const float4*)(hr + (tid << 2));
    float s = x.x + x.y + x.z + x.w;
    s = warp_sum(s);
    if (lane == 0) red[wid] = s;
    __syncthreads();
    float mu = (red[0] + red[1] + red[2] + red[3]) * (1.0f / DD);
    __syncthreads();

    float d0 = x.x - mu, d1 = x.y - mu, d2 = x.z - mu, d3 = x.w - mu;
    float vs = d0 * d0 + d1 * d1 + d2 * d2 + d3 * d3;
    vs = warp_sum(vs);
    if (lane == 0) red[wid] = vs;
    __syncthreads();
    float var = (red[0] + red[1] + red[2] + red[3]) * (1.0f / DD);
    float inv = rsqrtf(var + 1e-5f);

    float4 g4 = *(const float4*)(gw + (tid << 2));
    float4 b4 = *(const float4*)(gb + (tid << 2));
    float4 o;
    o.x = d0 * inv * g4.x + b4.x;
    o.y = d1 * inv * g4.y + b4.y;
    o.z = d2 * inv * g4.z + b4.z;
    o.w = d3 * inv * g4.w + b4.w;
    *(float4*)(out + (size_t)row * DD + (tid << 2)) = o;
}

// ---------------------------------------------------------------------------
// Host launcher
// ---------------------------------------------------------------------------
extern "C" void kernel_launch(void* const* d_in, const int* in_sizes, int n_in,
                              void* d_out, int out_size)
{
    const float* x     = (const float*)d_in[0];
    const float* edges = (const float*)d_in[1];
    const float* in_w  = (const float*)d_in[2];
    const float* in_b  = (const float*)d_in[3];
    const float* qw    = (const float*)d_in[4];
    const float* qb    = (const float*)d_in[5];
    const float* kw    = (const float*)d_in[6];
    const float* kb    = (const float*)d_in[7];
    const float* vw    = (const float*)d_in[8];
    const float* vb    = (const float*)d_in[9];
    const float* ow    = (const float*)d_in[10];
    const float* ob    = (const float*)d_in[11];
    const float* ew    = (const float*)d_in[12];
    // d_in[13] = eb: constant over j, cancels in softmax -> unused
    const float* ln_g  = (const float*)d_in[14];
    const float* ln_b  = (const float*)d_in[15];

    void* sp = nullptr;
    cudaGetSymbolAddress(&sp, g_scratch);
    float* h   = (float*)sp;
    float* qv  = h  + (size_t)MTOT * DD;
    float* kv  = qv + (size_t)MTOT * DD;
    float* vv  = kv + (size_t)MTOT * DD;
    float* att = vv + (size_t)MTOT * DD;

    const int ATTN_SMEM = (12288 + 64 * 65) * 4;  // 65792 B
    cudaFuncSetAttribute(attn_kernel,
                         cudaFuncAttributeMaxDynamicSharedMemorySize, ATTN_SMEM);

    dim3 gg(DD / 64, MTOT / 64);    // (8, 64)
    dim3 ga(HH, NN / 64, BB);       // (8, 16, 4)

    // h = x @ in_w + in_b
    gemm_bias_kernel<<<gg, 256>>>(x, in_w, in_b, nullptr, h, 128, DD);

    for (int l = 0; l < LL; l++) {
        const float* qwl = qw + (size_t)l * DD * DD;
        const float* kwl = kw + (size_t)l * DD * DD;
        const float* vwl = vw + (size_t)l * DD * DD;
        const float* owl = ow + (size_t)l * DD * DD;
        const float* qbl = qb + (size_t)l * DD;
        const float* kbl = kb + (size_t)l * DD;
        const float* vbl = vb + (size_t)l * DD;
        const float* obl = ob + (size_t)l * DD;
        const float* ewl = ew + (size_t)l * EE * HH;

        gemm_bias_kernel<<<gg, 256>>>(h, qwl, qbl, nullptr, qv, DD, DD);
        gemm_bias_kernel<<<gg, 256>>>(h, kwl, kbl, nullptr, kv, DD, DD);
        gemm_bias_kernel<<<gg, 256>>>(h, vwl, vbl, nullptr, vv, DD, DD);

        attn_kernel<<<ga, 256, ATTN_SMEM>>>(qv, kv, vv, edges, ewl, att);

        // h = h + att @ ow + ob   (residual fused)
        gemm_bias_kernel<<<gg, 256>>>(att, owl, obl, h, h, DD, DD);
    }

    ln_kernel<<<MTOT, 128>>>(h, ln_g, ln_b, (float*)d_out);
}

// round 2
// speedup vs baseline: 2.1328x; 2.1328x over previous
#include <cuda_runtime.h>
#include <math.h>

// Problem constants
#define BB    4
#define NN    1024
#define DD    512
#define HH    8
#define HDIM  64
#define EE    4
#define LL    3
#define MTOT  (BB*NN)   // 4096

// Scratch: h, q, k, v, att  (5 * 4096 * 512 floats = 42 MB)
__device__ float g_scratch[5ull * MTOT * DD];

// ---------------------------------------------------------------------------
// Helpers: tf32 convert + m16n8k8 tf32 mma
// ---------------------------------------------------------------------------
__device__ __forceinline__ unsigned f2tf(float x) {
    unsigned u;
    asm("cvt.rna.tf32.f32 %0, %1;" : "=r"(u) : "f"(x));
    return u;
}

__device__ __forceinline__ void mma_tf32(float c[4], const unsigned a[4],
                                         unsigned b0, unsigned b1) {
    asm volatile(
        "mma.sync.aligned.m16n8k8.row.col.f32.tf32.tf32.f32 "
        "{%0,%1,%2,%3}, {%4,%5,%6,%7}, {%8,%9}, {%0,%1,%2,%3};\n"
        : "+f"(c[0]), "+f"(c[1]), "+f"(c[2]), "+f"(c[3])
        : "r"(a[0]), "r"(a[1]), "r"(a[2]), "r"(a[3]), "r"(b0), "r"(b1));
}

// ---------------------------------------------------------------------------
// tf32 GEMM: C[M,Nn] = A[M,K] @ W[K,Nn] + bias (+ resid)
// BM=128, BN=64, BK=16. 256 threads = 8 warps (4 m-warps x 2 n-warps),
// warp tile 32x32 (2 m16 frags x 4 n8 frags).
// As: [m][k] pad 20 (conflict-free A-frag LDS). Bs: k-major [k][n] pad 68.
// Register-staged double buffer hides gmem latency.
// ---------------------------------------------------------------------------
#define GBM 128
#define GBN 64
#define GBK 16

__global__ __launch_bounds__(256) void gemm_tf32(
    const float* __restrict__ A, const float* __restrict__ W,
    const float* __restrict__ bias, const float* __restrict__ resid,
    float* __restrict__ C, int K, int Nn)
{
    __shared__ unsigned As[2][GBM][20];
    __shared__ unsigned Bs[2][GBK][68];

    const int tid = threadIdx.x;
    const int wid = tid >> 5, lane = tid & 31;
    const int wm = wid & 3, wn = wid >> 2;     // 4 x 2 warp grid
    const int qr = lane >> 2, qc = lane & 3;   // quad row / col
    const int m0 = blockIdx.y * GBM, n0 = blockIdx.x * GBN;

    // A tile load mapping: 512 float4 / 256 threads = 2 each
    const int ar0 = tid >> 2;                  // 0..63
    const int ak0 = (tid & 3) << 2;            // 0,4,8,12
    // B tile: 16x64 = 256 float4, 1 each
    const int bkr = tid >> 4;                  // 0..15
    const int bnc = (tid & 15) << 2;           // 0..60

    const float* Ab = A + (size_t)m0 * K;
    const float* Wb = W + n0;

    float4 a_reg0, a_reg1, b_reg;
    const int KS = K >> 4;

    // preload stage 0
    a_reg0 = *(const float4*)(Ab + (size_t)ar0 * K + ak0);
    a_reg1 = *(const float4*)(Ab + (size_t)(ar0 + 64) * K + ak0);
    b_reg  = *(const float4*)(Wb + (size_t)bkr * Nn + bnc);
    {
        unsigned u0 = f2tf(a_reg0.x), u1 = f2tf(a_reg0.y),
                 u2 = f2tf(a_reg0.z), u3 = f2tf(a_reg0.w);
        *(uint4*)&As[0][ar0][ak0] = make_uint4(u0, u1, u2, u3);
        u0 = f2tf(a_reg1.x); u1 = f2tf(a_reg1.y);
        u2 = f2tf(a_reg1.z); u3 = f2tf(a_reg1.w);
        *(uint4*)&As[0][ar0 + 64][ak0] = make_uint4(u0, u1, u2, u3);
        u0 = f2tf(b_reg.x); u1 = f2tf(b_reg.y);
        u2 = f2tf(b_reg.z); u3 = f2tf(b_reg.w);
        *(uint4*)&Bs[0][bkr][bnc] = make_uint4(u0, u1, u2, u3);
    }
    __syncthreads();

    float acc[2][4][4] = {};

    for (int ks = 0; ks < KS; ks++) {
        const int nxt = ks + 1;
        if (nxt < KS) {
            const int k0 = nxt << 4;
            a_reg0 = *(const float4*)(Ab + (size_t)ar0 * K + k0 + ak0);
            a_reg1 = *(const float4*)(Ab + (size_t)(ar0 + 64) * K + k0 + ak0);
            b_reg  = *(const float4*)(Wb + (size_t)(k0 + bkr) * Nn + bnc);
        }
        const int buf = ks & 1;
#pragma unroll
        for (int k8 = 0; k8 < 2; k8++) {
            unsigned af[2][4];
#pragma unroll
            for (int mf = 0; mf < 2; mf++) {
                const unsigned* ab = &As[buf][wm * 32 + mf * 16 + qr][k8 * 8 + qc];
                af[mf][0] = ab[0];
                af[mf][1] = ab[8 * 20];
                af[mf][2] = ab[4];
                af[mf][3] = ab[8 * 20 + 4];
            }
#pragma unroll
            for (int nf = 0; nf < 4; nf++) {
                const unsigned* bb = &Bs[buf][k8 * 8 + qc][wn * 32 + nf * 8 + qr];
                unsigned b0 = bb[0];
                unsigned b1 = bb[4 * 68];
                mma_tf32(acc[0][nf], af[0], b0, b1);
                mma_tf32(acc[1][nf], af[1], b0, b1);
            }
        }
        if (nxt < KS) {
            __syncthreads();
            unsigned u0 = f2tf(a_reg0.x), u1 = f2tf(a_reg0.y),
                     u2 = f2tf(a_reg0.z), u3 = f2tf(a_reg0.w);
            *(uint4*)&As[nxt & 1][ar0][ak0] = make_uint4(u0, u1, u2, u3);
            u0 = f2tf(a_reg1.x); u1 = f2tf(a_reg1.y);
            u2 = f2tf(a_reg1.z); u3 = f2tf(a_reg1.w);
            *(uint4*)&As[nxt & 1][ar0 + 64][ak0] = make_uint4(u0, u1, u2, u3);
            u0 = f2tf(b_reg.x); u1 = f2tf(b_reg.y);
            u2 = f2tf(b_reg.z); u3 = f2tf(b_reg.w);
            *(uint4*)&Bs[nxt & 1][bkr][bnc] = make_uint4(u0, u1, u2, u3);
            __syncthreads();
        }
    }

    // Epilogue
#pragma unroll
    for (int mf = 0; mf < 2; mf++) {
#pragma unroll
        for (int nf = 0; nf < 4; nf++) {
            const int col = n0 + wn * 32 + nf * 8 + (qc << 1);
            const float b0 = bias[col], b1 = bias[col + 1];
#pragma unroll
            for (int rr = 0; rr < 2; rr++) {
                const int row = m0 + wm * 32 + mf * 16 + qr + rr * 8;
                float o0 = acc[mf][nf][rr * 2 + 0] + b0;
                float o1 = acc[mf][nf][rr * 2 + 1] + b1;
                if (resid) {
                    const float* rp = resid + (size_t)row * Nn + col;
                    o0 += rp[0]; o1 += rp[1];
                }
                float2 ov = make_float2(o0, o1);
                *(float2*)(C + (size_t)row * Nn + col) = ov;
            }
        }
    }
}

// ---------------------------------------------------------------------------
// tf32 flash attention per (b, h, 64-row i-tile). 128 threads = 4 warps,
// warp w owns rows [w*16, w*16+16). j loop over 16 tiles of 64.
// Smem (tf32 bits): Qs[64][68] (i,d) | Ks[64][68] (j,d) | Vs[64][68] (d,j) |
//                   Ps[64][68] (i,j; per-warp 16-row slices)
// ---------------------------------------------------------------------------
__global__ __launch_bounds__(128) void attn_tf32(
    const float* __restrict__ q, const float* __restrict__ k,
    const float* __restrict__ v, const float* __restrict__ edges,
    const float* __restrict__ ewl, float* __restrict__ out)
{
    extern __shared__ unsigned sm[];
    unsigned* Qs = sm;                  // [64][68]
    unsigned* Ks = Qs + 64 * 68;        // [64][68]
    unsigned* Vs = Ks + 64 * 68;        // [64][68]
    unsigned* Ps = Vs + 64 * 68;        // [64][68]

    const int h = blockIdx.x, it = blockIdx.y, b = blockIdx.z;
    const int i0 = it << 6;
    const int tid = threadIdx.x;
    const int w = tid >> 5, lane = tid & 31;
    const int qr = lane >> 2, qc = lane & 3;

    const float ew0 = ewl[0 * HH + h], ew1 = ewl[1 * HH + h];
    const float ew2 = ewl[2 * HH + h], ew3 = ewl[3 * HH + h];

    // ---- load Q tile (i,d) with tf32 convert ----
    const float* qbase = q + ((size_t)(b * NN + i0)) * DD + h * HDIM;
#pragma unroll
    for (int i = 0; i < 8; i++) {
        const int vidx = tid + i * 128;
        const int row = vidx >> 4, c4 = (vidx & 15) << 2;
        float4 t = *(const float4*)(qbase + (size_t)row * DD + c4);
        *(uint4*)&Qs[row * 68 + c4] =
            make_uint4(f2tf(t.x), f2tf(t.y), f2tf(t.z), f2tf(t.w));
    }
    __syncthreads();

    // ---- Q fragments in registers: 8 k8-frags x 4 regs ----
    unsigned qf[8][4];
#pragma unroll
    for (int k8 = 0; k8 < 8; k8++) {
        const unsigned* qb2 = &Qs[(w * 16 + qr) * 68 + k8 * 8 + qc];
        qf[k8][0] = qb2[0];
        qf[k8][1] = qb2[8 * 68];
        qf[k8][2] = qb2[4];
        qf[k8][3] = qb2[8 * 68 + 4];
    }

    float m0v = -1e30f, m1v = -1e30f, l0v = 0.f, l1v = 0.f;
    float of[8][4] = {};

    const float* kbase = k + ((size_t)(b * NN)) * DD + h * HDIM;
    const float* vbase = v + ((size_t)(b * NN)) * DD + h * HDIM;
    const int gi = i0 + w * 16 + qr;          // global row (this thread, row0)
    const size_t erow0 = ((size_t)b * NN + gi) * NN;
    const size_t erow1 = ((size_t)b * NN + gi + 8) * NN;

    for (int j0 = 0; j0 < NN; j0 += 64) {
        __syncthreads();  // protect Ks/Vs (and Qs on first iter already synced)
        // ---- load K (j,d) direct, V transposed (d,j) ----
#pragma unroll
        for (int i = 0; i < 8; i++) {
            const int vidx = tid + i * 128;
            const int row = vidx >> 4, c4 = (vidx & 15) << 2;
            float4 t = *(const float4*)(kbase + (size_t)(j0 + row) * DD + c4);
            *(uint4*)&Ks[row * 68 + c4] =
                make_uint4(f2tf(t.x), f2tf(t.y), f2tf(t.z), f2tf(t.w));
            float4 tv = *(const float4*)(vbase + (size_t)(j0 + row) * DD + c4);
            Vs[(c4 + 0) * 68 + row] = f2tf(tv.x);
            Vs[(c4 + 1) * 68 + row] = f2tf(tv.y);
            Vs[(c4 + 2) * 68 + row] = f2tf(tv.z);
            Vs[(c4 + 3) * 68 + row] = f2tf(tv.w);
        }
        __syncthreads();

        // ---- S = Q K^T * 0.125 + edges . ew  (8 n8 frags) ----
        float s[8][4];
        const int gc0 = j0 + (qc << 1);
        float4 e00 = *(const float4*)(edges + (erow0 + gc0) * EE);
        float4 e01 = *(const float4*)(edges + (erow0 + gc0 + 1) * EE);
        float4 e10 = *(const float4*)(edges + (erow1 + gc0) * EE);
        float4 e11 = *(const float4*)(edges + (erow1 + gc0 + 1) * EE);
#pragma unroll
        for (int n8 = 0; n8 < 8; n8++) {
            float sd[4] = {};
#pragma unroll
            for (int k8 = 0; k8 < 8; k8++) {
                const unsigned* kb2 = &Ks[(n8 * 8 + qr) * 68 + k8 * 8 + qc];
                mma_tf32(sd, qf[k8], kb2[0], kb2[4]);
            }
            float4 f00 = e00, f01 = e01, f10 = e10, f11 = e11;
            if (n8 < 7) {
                const int gc = j0 + (n8 + 1) * 8 + (qc << 1);
                e00 = *(const float4*)(edges + (erow0 + gc) * EE);
                e01 = *(const float4*)(edges + (erow0 + gc + 1) * EE);
                e10 = *(const float4*)(edges + (erow1 + gc) * EE);
                e11 = *(const float4*)(edges + (erow1 + gc + 1) * EE);
            }
            s[n8][0] = sd[0] * 0.125f + f00.x * ew0 + f00.y * ew1 + f00.z * ew2 + f00.w * ew3;
            s[n8][1] = sd[1] * 0.125f + f01.x * ew0 + f01.y * ew1 + f01.z * ew2 + f01.w * ew3;
            s[n8][2] = sd[2] * 0.125f + f10.x * ew0 + f10.y * ew1 + f10.z * ew2 + f10.w * ew3;
            s[n8][3] = sd[3] * 0.125f + f11.x * ew0 + f11.y * ew1 + f11.z * ew2 + f11.w * ew3;
        }

        // ---- online softmax (rows qr and qr+8) ----
        float mt0 = -1e30f, mt1 = -1e30f;
#pragma unroll
        for (int n8 = 0; n8 < 8; n8++) {
            mt0 = fmaxf(mt0, fmaxf(s[n8][0], s[n8][1]));
            mt1 = fmaxf(mt1, fmaxf(s[n8][2], s[n8][3]));
        }
        mt0 = fmaxf(mt0, __shfl_xor_sync(0xffffffffu, mt0, 1));
        mt0 = fmaxf(mt0, __shfl_xor_sync(0xffffffffu, mt0, 2));
        mt1 = fmaxf(mt1, __shfl_xor_sync(0xffffffffu, mt1, 1));
        mt1 = fmaxf(mt1, __shfl_xor_sync(0xffffffffu, mt1, 2));
        const float mn0 = fmaxf(m0v, mt0), mn1 = fmaxf(m1v, mt1);
        const float f0 = __expf(m0v - mn0), f1 = __expf(m1v - mn1);
        m0v = mn0; m1v = mn1;

        float rs0 = 0.f, rs1 = 0.f;
#pragma unroll
        for (int n8 = 0; n8 < 8; n8++) {
            s[n8][0] = __expf(s[n8][0] - mn0);
            s[n8][1] = __expf(s[n8][1] - mn0);
            s[n8][2] = __expf(s[n8][2] - mn1);
            s[n8][3] = __expf(s[n8][3] - mn1);
            rs0 += s[n8][0] + s[n8][1];
            rs1 += s[n8][2] + s[n8][3];
        }
        rs0 += __shfl_xor_sync(0xffffffffu, rs0, 1);
        rs0 += __shfl_xor_sync(0xffffffffu, rs0, 2);
        rs1 += __shfl_xor_sync(0xffffffffu, rs1, 1);
        rs1 += __shfl_xor_sync(0xffffffffu, rs1, 2);
        l0v = l0v * f0 + rs0;
        l1v = l1v * f1 + rs1;

        // rescale O
#pragma unroll
        for (int n8 = 0; n8 < 8; n8++) {
            of[n8][0] *= f0; of[n8][1] *= f0;
            of[n8][2] *= f1; of[n8][3] *= f1;
        }

        // ---- stash P (tf32) to warp-private smem rows ----
#pragma unroll
        for (int n8 = 0; n8 < 8; n8++) {
            const int base0 = (w * 16 + qr) * 68 + n8 * 8 + (qc << 1);
            *(uint2*)&Ps[base0] = make_uint2(f2tf(s[n8][0]), f2tf(s[n8][1]));
            *(uint2*)&Ps[base0 + 8 * 68] = make_uint2(f2tf(s[n8][2]), f2tf(s[n8][3]));
        }
        __syncwarp();

        // ---- O += P @ V ----
#pragma unroll
        for (int k8 = 0; k8 < 8; k8++) {
            unsigned af[4];
            const unsigned* pb = &Ps[(w * 16 + qr) * 68 + k8 * 8 + qc];
            af[0] = pb[0];
            af[1] = pb[8 * 68];
            af[2] = pb[4];
            af[3] = pb[8 * 68 + 4];
#pragma unroll
            for (int n8 = 0; n8 < 8; n8++) {
                const unsigned* vb2 = &Vs[(n8 * 8 + qr) * 68 + k8 * 8 + qc];
                mma_tf32(of[n8], af, vb2[0], vb2[4]);
            }
        }
        __syncwarp();
    }

    // ---- epilogue: O / l ----
    float* obase = out + ((size_t)(b * NN + i0 + w * 16 + qr)) * DD + h * HDIM;
    const float inv0 = 1.0f / l0v, inv1 = 1.0f / l1v;
#pragma unroll
    for (int n8 = 0; n8 < 8; n8++) {
        const int col = n8 * 8 + (qc << 1);
        *(float2*)(obase + col) = make_float2(of[n8][0] * inv0, of[n8][1] * inv0);
        *(float2*)(obase + (size_t)8 * DD + col) =
            make_float2(of[n8][2] * inv1, of[n8][3] * inv1);
    }
}

// ---------------------------------------------------------------------------
// Row LayerNorm: 4096 rows x 512 cols, 128 threads/row.
// ---------------------------------------------------------------------------
__device__ __forceinline__ float warp_sum(float s) {
#pragma unroll
    for (int o = 16; o; o >>= 1) s += __shfl_xor_sync(0xffffffffu, s, o);
    return s;
}

__global__ __launch_bounds__(128) void ln_kernel(
    const float* __restrict__ hin, const float* __restrict__ gw,
    const float* __restrict__ gb, float* __restrict__ out)
{
    __shared__ float red[4];
    const int row = blockIdx.x;
    const int tid = threadIdx.x;
    const int wid = tid >> 5, lane = tid & 31;
    const float* hr = hin + (size_t)row * DD;

    float4 x = *(const float4*)(hr + (tid << 2));
    float s = x.x + x.y + x.z + x.w;
    s = warp_sum(s);
    if (lane == 0) red[wid] = s;
    __syncthreads();
    float mu = (red[0] + red[1] + red[2] + red[3]) * (1.0f / DD);
    __syncthreads();

    float d0 = x.x - mu, d1 = x.y - mu, d2 = x.z - mu, d3 = x.w - mu;
    float vs = d0 * d0 + d1 * d1 + d2 * d2 + d3 * d3;
    vs = warp_sum(vs);
    if (lane == 0) red[wid] = vs;
    __syncthreads();
    float var = (red[0] + red[1] + red[2] + red[3]) * (1.0f / DD);
    float inv = rsqrtf(var + 1e-5f);

    float4 g4 = *(const float4*)(gw + (tid << 2));
    float4 b4 = *(const float4*)(gb + (tid << 2));
    float4 o;
    o.x = d0 * inv * g4.x + b4.x;
    o.y = d1 * inv * g4.y + b4.y;
    o.z = d2 * inv * g4.z + b4.z;
    o.w = d3 * inv * g4.w + b4.w;
    *(float4*)(out + (size_t)row * DD + (tid << 2)) = o;
}

// ---------------------------------------------------------------------------
// Host launcher
// ---------------------------------------------------------------------------
extern "C" void kernel_launch(void* const* d_in, const int* in_sizes, int n_in,
                              void* d_out, int out_size)
{
    const float* x     = (const float*)d_in[0];
    const float* edges = (const float*)d_in[1];
    const float* in_w  = (const float*)d_in[2];
    const float* in_b  = (const float*)d_in[3];
    const float* qw    = (const float*)d_in[4];
    const float* qb    = (const float*)d_in[5];
    const float* kw    = (const float*)d_in[6];
    const float* kb    = (const float*)d_in[7];
    const float* vw    = (const float*)d_in[8];
    const float* vb    = (const float*)d_in[9];
    const float* ow    = (const float*)d_in[10];
    const float* ob    = (const float*)d_in[11];
    const float* ew    = (const float*)d_in[12];
    // d_in[13] = eb: constant over j, cancels in softmax -> unused
    const float* ln_g  = (const float*)d_in[14];
    const float* ln_b  = (const float*)d_in[15];

    void* sp = nullptr;
    cudaGetSymbolAddress(&sp, g_scratch);
    float* h   = (float*)sp;
    float* qv  = h  + (size_t)MTOT * DD;
    float* kv  = qv + (size_t)MTOT * DD;
    float* vv  = kv + (size_t)MTOT * DD;
    float* att = vv + (size_t)MTOT * DD;

    const int ATTN_SMEM = 4 * 64 * 68 * 4;  // 69632 B
    static int s_init = 0;
    if (!s_init) {
        cudaFuncSetAttribute(attn_tf32,
                             cudaFuncAttributeMaxDynamicSharedMemorySize,
                             ATTN_SMEM);
        s_init = 1;
    }

    dim3 gg(DD / GBN, MTOT / GBM);  // (8, 32)
    dim3 ga(HH, NN / 64, BB);       // (8, 16, 4)

    // h = x @ in_w + in_b
    gemm_tf32<<<gg, 256>>>(x, in_w, in_b, nullptr, h, 128, DD);

    for (int l = 0; l < LL; l++) {
        const float* qwl = qw + (size_t)l * DD * DD;
        const float* kwl = kw + (size_t)l * DD * DD;
        const float* vwl = vw + (size_t)l * DD * DD;
        const float* owl = ow + (size_t)l * DD * DD;
        const float* qbl = qb + (size_t)l * DD;
        const float* kbl = kb + (size_t)l * DD;
        const float* vbl = vb + (size_t)l * DD;
        const float* obl = ob + (size_t)l * DD;
        const float* ewl = ew + (size_t)l * EE * HH;

        gemm_tf32<<<gg, 256>>>(h, qwl, qbl, nullptr, qv, DD, DD);
        gemm_tf32<<<gg, 256>>>(h, kwl, kbl, nullptr, kv, DD, DD);
        gemm_tf32<<<gg, 256>>>(h, vwl, vbl, nullptr, vv, DD, DD);

        attn_tf32<<<ga, 128, ATTN_SMEM>>>(qv, kv, vv, edges, ewl, att);

        // h = h + att @ ow + ob   (residual fused)
        gemm_tf32<<<gg, 256>>>(att, owl, obl, h, h, DD, DD);
    }

    ln_kernel<<<MTOT, 128>>>(h, ln_g, ln_b, (float*)d_out);
}

// round 3
// speedup vs baseline: 2.3029x; 1.0797x over previous
#include <cuda_runtime.h>
#include <math.h>

// Problem constants
#define BB    4
#define NN    1024
#define DD    512
#define HH    8
#define HDIM  64
#define EE    4
#define LL    3
#define MTOT  (BB*NN)   // 4096

// Scratch: h, q, k, vt, att
__device__ float g_scratch[5ull * MTOT * DD];

// ---------------------------------------------------------------------------
// Helpers
// ---------------------------------------------------------------------------
__device__ __forceinline__ unsigned f2tf(float x) {
    unsigned u;
    asm("cvt.rna.tf32.f32 %0, %1;" : "=r"(u) : "f"(x));
    return u;
}

__device__ __forceinline__ void mma_tf32(float c[4], const unsigned a[4],
                                         unsigned b0, unsigned b1) {
    asm volatile(
        "mma.sync.aligned.m16n8k8.row.col.f32.tf32.tf32.f32 "
        "{%0,%1,%2,%3}, {%4,%5,%6,%7}, {%8,%9}, {%0,%1,%2,%3};\n"
        : "+f"(c[0]), "+f"(c[1]), "+f"(c[2]), "+f"(c[3])
        : "r"(a[0]), "r"(a[1]), "r"(a[2]), "r"(a[3]), "r"(b0), "r"(b1));
}

// ---------------------------------------------------------------------------
// tf32 GEMM with paired-k layouts.
// BM=128, BN=64, BK=32. 256 threads, 8 warps (4m x 2n), warp tile 32x32.
// Pair layout within each 8-k group: pos(k) = 2*(k&3) + (k>>2); a fragment's
// (k, k+4) pair is one LDS.64.
// As: [128 m][40] (32 k-perm + pad).  Bs: [64 n][40].
// gridDim.z selects among up to 3 weight sets (fused QKV); z == v_index
// writes C transposed (vt[col][m], stride MTOT).
// ---------------------------------------------------------------------------
#define ASTR 40
#define BSTR 40
#define A_WORDS (128*ASTR)
#define B_WORDS (64*BSTR)

__global__ __launch_bounds__(256) void gemm_tf32(
    const float* __restrict__ A,
    const float* __restrict__ W0, const float* __restrict__ W1,
    const float* __restrict__ W2,
    const float* __restrict__ bs0, const float* __restrict__ bs1,
    const float* __restrict__ bs2,
    float* __restrict__ C0, float* __restrict__ C1, float* __restrict__ C2,
    const float* __restrict__ resid, int K, int v_index)
{
    extern __shared__ unsigned gsm[];
    unsigned* As = gsm;                  // [2][A_WORDS]
    unsigned* Bs = gsm + 2 * A_WORDS;    // [2][B_WORDS]

    const int z = blockIdx.z;
    const float* W    = (z == 0) ? W0  : (z == 1) ? W1  : W2;
    const float* bias = (z == 0) ? bs0 : (z == 1) ? bs1 : bs2;
    float*       C    = (z == 0) ? C0  : (z == 1) ? C1  : C2;
    const bool   vt   = (z == v_index);

    const int tid = threadIdx.x;
    const int wid = tid >> 5, lane = tid & 31;
    const int wm = wid & 3, wn = wid >> 2;
    const int qr = lane >> 2, qc = lane & 3;
    const int m0 = blockIdx.y * 128, n0 = blockIdx.x * 64;

    // A loader: thread -> (m row set, k slot). 128 m x 8 slots, 4 m rows each.
    const int am  = tid >> 3;                 // 0..31 (+32*mi)
    const int aks = tid & 7;
    const int ag  = aks >> 1, akb = (aks & 1) * 2;
    const int a_k = ag * 8 + akb;             // 0,2,8,10,16,18,24,26
    // B loader: thread -> (n, kq). 64 n x 4 kq.
    const int bn = tid & 63, bkq = tid >> 6;  // kq 0..3

    const float* Ab = A + (size_t)m0 * K;
    const float* Wb = W + n0;
    const int KS = K >> 5;

    float2 al[4], ah[4];
    float  bl[4], bh[4];

    // preload tile 0
#pragma unroll
    for (int mi = 0; mi < 4; mi++) {
        const float* p = Ab + (size_t)(am + 32 * mi) * K + a_k;
        al[mi] = *(const float2*)p;
        ah[mi] = *(const float2*)(p + 4);
    }
#pragma unroll
    for (int g = 0; g < 4; g++) {
        bl[g] = Wb[(size_t)(g * 8 + bkq) * DD + bn];
        bh[g] = Wb[(size_t)(g * 8 + bkq + 4) * DD + bn];
    }
#pragma unroll
    for (int mi = 0; mi < 4; mi++)
        *(uint4*)&As[(am + 32 * mi) * ASTR + ag * 8 + 2 * akb] =
            make_uint4(f2tf(al[mi].x), f2tf(ah[mi].x),
                       f2tf(al[mi].y), f2tf(ah[mi].y));
#pragma unroll
    for (int g = 0; g < 4; g++)
        *(uint2*)&Bs[bn * BSTR + g * 8 + 2 * bkq] =
            make_uint2(f2tf(bl[g]), f2tf(bh[g]));
    __syncthreads();

    float acc[2][4][4] = {};

    for (int ks = 0; ks < KS; ks++) {
        const int nxt = ks + 1;
        if (nxt < KS) {
            const int k0 = nxt << 5;
#pragma unroll
            for (int mi = 0; mi < 4; mi++) {
                const float* p = Ab + (size_t)(am + 32 * mi) * K + k0 + a_k;
                al[mi] = *(const float2*)p;
                ah[mi] = *(const float2*)(p + 4);
            }
#pragma unroll
            for (int g = 0; g < 4; g++) {
                bl[g] = Wb[(size_t)(k0 + g * 8 + bkq) * DD + bn];
                bh[g] = Wb[(size_t)(k0 + g * 8 + bkq + 4) * DD + bn];
            }
        }
        const unsigned* Ab_s = As + (ks & 1) * A_WORDS;
        const unsigned* Bb_s = Bs + (ks & 1) * B_WORDS;
#pragma unroll
        for (int k8 = 0; k8 < 4; k8++) {
            unsigned af[2][4];
#pragma unroll
            for (int mf = 0; mf < 2; mf++) {
                const unsigned* ap =
                    &Ab_s[(wm * 32 + mf * 16 + qr) * ASTR + k8 * 8 + 2 * qc];
                uint2 lo = *(const uint2*)ap;
                uint2 hi = *(const uint2*)(ap + 8 * ASTR);
                af[mf][0] = lo.x; af[mf][1] = hi.x;
                af[mf][2] = lo.y; af[mf][3] = hi.y;
            }
#pragma unroll
            for (int nf = 0; nf < 4; nf++) {
                uint2 bb = *(const uint2*)
                    &Bb_s[(wn * 32 + nf * 8 + qr) * BSTR + k8 * 8 + 2 * qc];
                mma_tf32(acc[0][nf], af[0], bb.x, bb.y);
                mma_tf32(acc[1][nf], af[1], bb.x, bb.y);
            }
        }
        if (nxt < KS) {
            unsigned* Aw = As + (nxt & 1) * A_WORDS;
            unsigned* Bw = Bs + (nxt & 1) * B_WORDS;
#pragma unroll
            for (int mi = 0; mi < 4; mi++)
                *(uint4*)&Aw[(am + 32 * mi) * ASTR + ag * 8 + 2 * akb] =
                    make_uint4(f2tf(al[mi].x), f2tf(ah[mi].x),
                               f2tf(al[mi].y), f2tf(ah[mi].y));
#pragma unroll
            for (int g = 0; g < 4; g++)
                *(uint2*)&Bw[bn * BSTR + g * 8 + 2 * bkq] =
                    make_uint2(f2tf(bl[g]), f2tf(bh[g]));
            __syncthreads();
        }
    }

    // Epilogue
#pragma unroll
    for (int mf = 0; mf < 2; mf++) {
#pragma unroll
        for (int nf = 0; nf < 4; nf++) {
            const int col = n0 + wn * 32 + nf * 8 + (qc << 1);
            const float b0 = bias[col], b1 = bias[col + 1];
#pragma unroll
            for (int rr = 0; rr < 2; rr++) {
                const int row = m0 + wm * 32 + mf * 16 + qr + rr * 8;
                float o0 = acc[mf][nf][rr * 2 + 0] + b0;
                float o1 = acc[mf][nf][rr * 2 + 1] + b1;
                if (resid) {
                    const float* rp = resid + (size_t)row * DD + col;
                    o0 += rp[0]; o1 += rp[1];
                }
                if (vt) {
                    C[(size_t)col * MTOT + row]       = o0;
                    C[(size_t)(col + 1) * MTOT + row] = o1;
                } else {
                    *(float2*)(C + (size_t)row * DD + col) =
                        make_float2(o0, o1);
                }
            }
        }
    }
}

// ---------------------------------------------------------------------------
// tf32 flash attention, paired-k layouts.
// Block = (b, h, 64-row i-tile), 128 threads / 4 warps, warp = 16 i-rows.
// Qs[i][perm(d)], Ks[j][perm(d)], Vs[d][perm(j)] (V read from vt transposed),
// Ps[i][j] plain. All row stride 72 words.
// ---------------------------------------------------------------------------
#define XSTR 72

__global__ __launch_bounds__(128) void attn_tf32(
    const float* __restrict__ q, const float* __restrict__ k,
    const float* __restrict__ vt, const float* __restrict__ edges,
    const float* __restrict__ ewl, float* __restrict__ out)
{
    extern __shared__ unsigned sm[];
    unsigned* Qs = sm;                  // [64][72]
    unsigned* Ks = Qs + 64 * XSTR;
    unsigned* Vs = Ks + 64 * XSTR;
    unsigned* Ps = Vs + 64 * XSTR;

    const int h = blockIdx.x, it = blockIdx.y, b = blockIdx.z;
    const int i0 = it << 6;
    const int tid = threadIdx.x;
    const int w = tid >> 5, lane = tid & 31;
    const int qr = lane >> 2, qc = lane & 3;

    // pair-tile loader mapping: 64 rows x 16 slots, 8 rows per thread
    const int lr0 = tid >> 4;                 // 0..7 (+8i)
    const int lks = tid & 15;
    const int lg = lks >> 1, lkb = (lks & 1) * 2;
    const int l_k = lg * 8 + lkb;

    const float ew0 = ewl[0 * HH + h], ew1 = ewl[1 * HH + h];
    const float ew2 = ewl[2 * HH + h], ew3 = ewl[3 * HH + h];

    // ---- load Q tile into pair layout ----
    const float* qbase = q + ((size_t)(b * NN + i0)) * DD + h * HDIM;
#pragma unroll
    for (int i = 0; i < 8; i++) {
        const int r = lr0 + 8 * i;
        const float* p = qbase + (size_t)r * DD + l_k;
        float2 lo = *(const float2*)p, hi = *(const float2*)(p + 4);
        *(uint4*)&Qs[r * XSTR + lg * 8 + 2 * lkb] =
            make_uint4(f2tf(lo.x), f2tf(hi.x), f2tf(lo.y), f2tf(hi.y));
    }
    __syncthreads();

    unsigned qf[8][4];
#pragma unroll
    for (int k8 = 0; k8 < 8; k8++) {
        const unsigned* qp = &Qs[(w * 16 + qr) * XSTR + k8 * 8 + 2 * qc];
        uint2 lo = *(const uint2*)qp;
        uint2 hi = *(const uint2*)(qp + 8 * XSTR);
        qf[k8][0] = lo.x; qf[k8][1] = hi.x;
        qf[k8][2] = lo.y; qf[k8][3] = hi.y;
    }

    float m0v = -1e30f, m1v = -1e30f, l0v = 0.f, l1v = 0.f;
    float of[8][4] = {};

    const float* kbase = k + ((size_t)(b * NN)) * DD + h * HDIM;
    const float* vtb = vt + ((size_t)(h * HDIM)) * MTOT + b * NN;
    const int gi = i0 + w * 16 + qr;
    const size_t erow0 = ((size_t)b * NN + gi) * NN;
    const size_t erow1 = ((size_t)b * NN + gi + 8) * NN;

    for (int j0 = 0; j0 < NN; j0 += 64) {
        __syncthreads();
        // K: rows j, pair over d
#pragma unroll
        for (int i = 0; i < 8; i++) {
            const int r = lr0 + 8 * i;
            const float* p = kbase + (size_t)(j0 + r) * DD + l_k;
            float2 lo = *(const float2*)p, hi = *(const float2*)(p + 4);
            *(uint4*)&Ks[r * XSTR + lg * 8 + 2 * lkb] =
                make_uint4(f2tf(lo.x), f2tf(hi.x), f2tf(lo.y), f2tf(hi.y));
        }
        // V: rows d (from vt), pair over j
#pragma unroll
        for (int i = 0; i < 8; i++) {
            const int r = lr0 + 8 * i;   // d
            const float* p = vtb + (size_t)r * MTOT + j0 + l_k;
            float2 lo = *(const float2*)p, hi = *(const float2*)(p + 4);
            *(uint4*)&Vs[r * XSTR + lg * 8 + 2 * lkb] =
                make_uint4(f2tf(lo.x), f2tf(hi.x), f2tf(lo.y), f2tf(hi.y));
        }
        __syncthreads();

        // ---- S = Q K^T * 0.125 + edges . ew ----
        float s[8][4];
        const int gc0 = j0 + (qc << 1);
        float4 e00 = *(const float4*)(edges + (erow0 + gc0) * EE);
        float4 e01 = *(const float4*)(edges + (erow0 + gc0 + 1) * EE);
        float4 e10 = *(const float4*)(edges + (erow1 + gc0) * EE);
        float4 e11 = *(const float4*)(edges + (erow1 + gc0 + 1) * EE);
#pragma unroll
        for (int n8 = 0; n8 < 8; n8++) {
            float sd[4] = {};
            const unsigned* kp = &Ks[(n8 * 8 + qr) * XSTR + 2 * qc];
#pragma unroll
            for (int k8 = 0; k8 < 8; k8++) {
                uint2 kb2 = *(const uint2*)(kp + k8 * 8);
                mma_tf32(sd, qf[k8], kb2.x, kb2.y);
            }
            float4 f00 = e00, f01 = e01, f10 = e10, f11 = e11;
            if (n8 < 7) {
                const int gc = j0 + (n8 + 1) * 8 + (qc << 1);
                e00 = *(const float4*)(edges + (erow0 + gc) * EE);
                e01 = *(const float4*)(edges + (erow0 + gc + 1) * EE);
                e10 = *(const float4*)(edges + (erow1 + gc) * EE);
                e11 = *(const float4*)(edges + (erow1 + gc + 1) * EE);
            }
            s[n8][0] = sd[0] * 0.125f + f00.x * ew0 + f00.y * ew1 + f00.z * ew2 + f00.w * ew3;
            s[n8][1] = sd[1] * 0.125f + f01.x * ew0 + f01.y * ew1 + f01.z * ew2 + f01.w * ew3;
            s[n8][2] = sd[2] * 0.125f + f10.x * ew0 + f10.y * ew1 + f10.z * ew2 + f10.w * ew3;
            s[n8][3] = sd[3] * 0.125f + f11.x * ew0 + f11.y * ew1 + f11.z * ew2 + f11.w * ew3;
        }

        // ---- online softmax ----
        float mt0 = -1e30f, mt1 = -1e30f;
#pragma unroll
        for (int n8 = 0; n8 < 8; n8++) {
            mt0 = fmaxf(mt0, fmaxf(s[n8][0], s[n8][1]));
            mt1 = fmaxf(mt1, fmaxf(s[n8][2], s[n8][3]));
        }
        mt0 = fmaxf(mt0, __shfl_xor_sync(0xffffffffu, mt0, 1));
        mt0 = fmaxf(mt0, __shfl_xor_sync(0xffffffffu, mt0, 2));
        mt1 = fmaxf(mt1, __shfl_xor_sync(0xffffffffu, mt1, 1));
        mt1 = fmaxf(mt1, __shfl_xor_sync(0xffffffffu, mt1, 2));
        const float mn0 = fmaxf(m0v, mt0), mn1 = fmaxf(m1v, mt1);
        const float f0 = __expf(m0v - mn0), f1 = __expf(m1v - mn1);
        m0v = mn0; m1v = mn1;

        float rs0 = 0.f, rs1 = 0.f;
#pragma unroll
        for (int n8 = 0; n8 < 8; n8++) {
            s[n8][0] = __expf(s[n8][0] - mn0);
            s[n8][1] = __expf(s[n8][1] - mn0);
            s[n8][2] = __expf(s[n8][2] - mn1);
            s[n8][3] = __expf(s[n8][3] - mn1);
            rs0 += s[n8][0] + s[n8][1];
            rs1 += s[n8][2] + s[n8][3];
        }
        rs0 += __shfl_xor_sync(0xffffffffu, rs0, 1);
        rs0 += __shfl_xor_sync(0xffffffffu, rs0, 2);
        rs1 += __shfl_xor_sync(0xffffffffu, rs1, 1);
        rs1 += __shfl_xor_sync(0xffffffffu, rs1, 2);
        l0v = l0v * f0 + rs0;
        l1v = l1v * f1 + rs1;

#pragma unroll
        for (int n8 = 0; n8 < 8; n8++) {
            of[n8][0] *= f0; of[n8][1] *= f0;
            of[n8][2] *= f1; of[n8][3] *= f1;
        }

        // ---- stash P (tf32) to warp-private Ps rows, plain layout ----
#pragma unroll
        for (int n8 = 0; n8 < 8; n8++) {
            const int base0 = (w * 16 + qr) * XSTR + n8 * 8 + (qc << 1);
            *(uint2*)&Ps[base0] = make_uint2(f2tf(s[n8][0]), f2tf(s[n8][1]));
            *(uint2*)&Ps[base0 + 8 * XSTR] =
                make_uint2(f2tf(s[n8][2]), f2tf(s[n8][3]));
        }
        __syncwarp();

        // ---- O += P @ V ----
#pragma unroll
        for (int k8 = 0; k8 < 8; k8++) {
            unsigned af[4];
            const unsigned* pb = &Ps[(w * 16 + qr) * XSTR + k8 * 8 + qc];
            af[0] = pb[0];
            af[1] = pb[8 * XSTR];
            af[2] = pb[4];
            af[3] = pb[8 * XSTR + 4];
#pragma unroll
            for (int n8 = 0; n8 < 8; n8++) {
                uint2 vb = *(const uint2*)
                    &Vs[(n8 * 8 + qr) * XSTR + k8 * 8 + 2 * qc];
                mma_tf32(of[n8], af, vb.x, vb.y);
            }
        }
        __syncwarp();
    }

    // ---- epilogue ----
    float* obase = out + ((size_t)(b * NN + i0 + w * 16 + qr)) * DD + h * HDIM;
    const float inv0 = 1.0f / l0v, inv1 = 1.0f / l1v;
#pragma unroll
    for (int n8 = 0; n8 < 8; n8++) {
        const int col = n8 * 8 + (qc << 1);
        *(float2*)(obase + col) = make_float2(of[n8][0] * inv0, of[n8][1] * inv0);
        *(float2*)(obase + (size_t)8 * DD + col) =
            make_float2(of[n8][2] * inv1, of[n8][3] * inv1);
    }
}

// ---------------------------------------------------------------------------
// Row LayerNorm
// ---------------------------------------------------------------------------
__device__ __forceinline__ float warp_sum(float s) {
#pragma unroll
    for (int o = 16; o; o >>= 1) s += __shfl_xor_sync(0xffffffffu, s, o);
    return s;
}

__global__ __launch_bounds__(128) void ln_kernel(
    const float* __restrict__ hin, const float* __restrict__ gw,
    const float* __restrict__ gb, float* __restrict__ out)
{
    __shared__ float red[4];
    const int row = blockIdx.x;
    const int tid = threadIdx.x;
    const int wid = tid >> 5, lane = tid & 31;
    const float* hr = hin + (size_t)row * DD;

    float4 x = *(const float4*)(hr + (tid << 2));
    float s = x.x + x.y + x.z + x.w;
    s = warp_sum(s);
    if (lane == 0) red[wid] = s;
    __syncthreads();
    float mu = (red[0] + red[1] + red[2] + red[3]) * (1.0f / DD);
    __syncthreads();

    float d0 = x.x - mu, d1 = x.y - mu, d2 = x.z - mu, d3 = x.w - mu;
    float vs = d0 * d0 + d1 * d1 + d2 * d2 + d3 * d3;
    vs = warp_sum(vs);
    if (lane == 0) red[wid] = vs;
    __syncthreads();
    float var = (red[0] + red[1] + red[2] + red[3]) * (1.0f / DD);
    float inv = rsqrtf(var + 1e-5f);

    float4 g4 = *(const float4*)(gw + (tid << 2));
    float4 b4 = *(const float4*)(gb + (tid << 2));
    float4 o;
    o.x = d0 * inv * g4.x + b4.x;
    o.y = d1 * inv * g4.y + b4.y;
    o.z = d2 * inv * g4.z + b4.z;
    o.w = d3 * inv * g4.w + b4.w;
    *(float4*)(out + (size_t)row * DD + (tid << 2)) = o;
}

// ---------------------------------------------------------------------------
// Host launcher
// ---------------------------------------------------------------------------
extern "C" void kernel_launch(void* const* d_in, const int* in_sizes, int n_in,
                              void* d_out, int out_size)
{
    const float* x     = (const float*)d_in[0];
    const float* edges = (const float*)d_in[1];
    const float* in_w  = (const float*)d_in[2];
    const float* in_b  = (const float*)d_in[3];
    const float* qw    = (const float*)d_in[4];
    const float* qb    = (const float*)d_in[5];
    const float* kw    = (const float*)d_in[6];
    const float* kb    = (const float*)d_in[7];
    const float* vw    = (const float*)d_in[8];
    const float* vb    = (const float*)d_in[9];
    const float* ow    = (const float*)d_in[10];
    const float* ob    = (const float*)d_in[11];
    const float* ew    = (const float*)d_in[12];
    // d_in[13] = eb: constant over j, cancels in softmax -> unused
    const float* ln_g  = (const float*)d_in[14];
    const float* ln_b  = (const float*)d_in[15];

    void* sp = nullptr;
    cudaGetSymbolAddress(&sp, g_scratch);
    float* h   = (float*)sp;
    float* qv  = h  + (size_t)MTOT * DD;
    float* kv  = qv + (size_t)MTOT * DD;
    float* vtb = kv + (size_t)MTOT * DD;   // V transposed: [DD][MTOT]
    float* att = vtb + (size_t)MTOT * DD;

    const int GEMM_SMEM = (2 * A_WORDS + 2 * B_WORDS) * 4;  // 61440
    const int ATTN_SMEM = 4 * 64 * XSTR * 4;                // 73728
    static int s_init = 0;
    if (!s_init) {
        cudaFuncSetAttribute(gemm_tf32,
                             cudaFuncAttributeMaxDynamicSharedMemorySize,
                             GEMM_SMEM);
        cudaFuncSetAttribute(attn_tf32,
                             cudaFuncAttributeMaxDynamicSharedMemorySize,
                             ATTN_SMEM);
        s_init = 1;
    }

    dim3 g1(DD / 64, MTOT / 128, 1);   // (8, 32)
    dim3 g3(DD / 64, MTOT / 128, 3);
    dim3 ga(HH, NN / 64, BB);          // (8, 16, 4)

    // h = x @ in_w + in_b
    gemm_tf32<<<g1, 256, GEMM_SMEM>>>(x, in_w, in_w, in_w, in_b, in_b, in_b,
                                      h, h, h, nullptr, 128, -1);

    for (int l = 0; l < LL; l++) {
        const float* qwl = qw + (size_t)l * DD * DD;
        const float* kwl = kw + (size_t)l * DD * DD;
        const float* vwl = vw + (size_t)l * DD * DD;
        const float* owl = ow + (size_t)l * DD * DD;
        const float* qbl = qb + (size_t)l * DD;
        const float* kbl = kb + (size_t)l * DD;
        const float* vbl = vb + (size_t)l * DD;
        const float* obl = ob + (size_t)l * DD;
        const float* ewl = ew + (size_t)l * EE * HH;

        // fused Q,K,V projections; V written transposed (vt layout)
        gemm_tf32<<<g3, 256, GEMM_SMEM>>>(h, qwl, kwl, vwl, qbl, kbl, vbl,
                                          qv, kv, vtb, nullptr, DD, 2);

        attn_tf32<<<ga, 128, ATTN_SMEM>>>(qv, kv, vtb, edges, ewl, att);

        // h = h + att @ ow + ob
        gemm_tf32<<<g1, 256, GEMM_SMEM>>>(att, owl, owl, owl, obl, obl, obl,
                                          h, h, h, h, DD, -1);
    }

    ln_kernel<<<MTOT, 128>>>(h, ln_g, ln_b, (float*)d_out);
}

// round 4
// speedup vs baseline: 3.0470x; 1.3231x over previous
#include <cuda_runtime.h>
#include <cuda_fp16.h>
#include <math.h>

// Problem constants
#define BB    4
#define NN    1024
#define DD    512
#define HH    8
#define HDIM  64
#define EE    4
#define LL    3
#define MTOT  (BB*NN)   // 4096

// Scratch (bytes): h fp32 8MB | q,k,vt,att half 4MB each | weights half ~6.4MB
__device__ __align__(256) unsigned char g_scratch[31588352];

// ---------------------------------------------------------------------------
// Helpers
// ---------------------------------------------------------------------------
__device__ __forceinline__ unsigned packh2(float lo, float hi) {
    __half2 h = __floats2half2_rn(lo, hi);
    return *reinterpret_cast<unsigned*>(&h);
}

__device__ __forceinline__ void mma_f16(float c[4], const unsigned a[4],
                                        unsigned b0, unsigned b1) {
    asm volatile(
        "mma.sync.aligned.m16n8k16.row.col.f32.f16.f16.f32 "
        "{%0,%1,%2,%3}, {%4,%5,%6,%7}, {%8,%9}, {%0,%1,%2,%3};\n"
        : "+f"(c[0]), "+f"(c[1]), "+f"(c[2]), "+f"(c[3])
        : "r"(a[0]), "r"(a[1]), "r"(a[2]), "r"(a[3]), "r"(b0), "r"(b1));
}

// ---------------------------------------------------------------------------
// Weight transpose + fp16 convert: dst[n][k] = (half)src[k][n]
// grid (N/32, K/32, batch), 256 threads
// ---------------------------------------------------------------------------
__global__ void transpose_w(const float* __restrict__ src,
                            __half* __restrict__ dst, int K, int N)
{
    __shared__ float t[32][33];
    const size_t off = (size_t)blockIdx.z * K * N;
    src += off; dst += off;
    const int k0 = blockIdx.y * 32, n0 = blockIdx.x * 32;
    const int c = threadIdx.x & 31, r0 = threadIdx.x >> 5;
#pragma unroll
    for (int i = 0; i < 4; i++) {
        int r = r0 + i * 8;
        t[r][c] = src[(size_t)(k0 + r) * N + n0 + c];
    }
    __syncthreads();
#pragma unroll
    for (int i = 0; i < 4; i++) {
        int r = r0 + i * 8;
        dst[(size_t)(n0 + r) * K + k0 + c] = __float2half(t[c][r]);
    }
}

// ---------------------------------------------------------------------------
// fp16 GEMM: C[M,512] = A[M,K] @ Wh^T + bias (+resid).
// BM=128 BN=128 BK=32. 8 warps (4m x 2n), warp tile 32x64.
// Smem rows = 16 half2-words pair-permuted per k16 group, stride AST=24.
// Pair perm: word w (0..7 in group) -> slot 2*(w&3)+(w>>2), so an mma
// fragment's (k,k+8) word pair is one LDS.64, conflict-free at stride 24.
// AHALF: A is __half[M][K], else float[M][K].
// chalf: C is half (q/k/v); z==tindex writes transposed half [col][MTOT].
// ---------------------------------------------------------------------------
#define AST 24
#define TWORDS (128*AST)

template<int AHALF>
__global__ __launch_bounds__(256, 2) void gemm_h(
    const void* __restrict__ Av,
    const __half* __restrict__ Wh0, const __half* __restrict__ Wh1,
    const __half* __restrict__ Wh2,
    const float* __restrict__ bs0, const float* __restrict__ bs1,
    const float* __restrict__ bs2,
    void* __restrict__ C0, void* __restrict__ C1, void* __restrict__ C2,
    const float* __restrict__ resid, int K, int chalf, int tindex)
{
    __shared__ unsigned As[2][TWORDS];
    __shared__ unsigned Bs[2][TWORDS];

    const int z = blockIdx.z;
    const __half* Wh   = (z == 0) ? Wh0 : (z == 1) ? Wh1 : Wh2;
    const float*  bias = (z == 0) ? bs0 : (z == 1) ? bs1 : bs2;
    void*         C    = (z == 0) ? C0  : (z == 1) ? C1  : C2;

    const int tid = threadIdx.x;
    const int wid = tid >> 5, lane = tid & 31;
    const int wm = wid & 3, wn = wid >> 2;
    const int qr = lane >> 2, qc = lane & 3;
    const int m0 = blockIdx.y * 128, n0 = blockIdx.x * 128;
    const int KS = K >> 5;

    // loader index maps
    const int hr = tid >> 1, hg = tid & 1;            // fp16 A / B: 1 task
    const int fr = tid >> 2, fg = (tid >> 1) & 1, fq = tid & 1;  // fp32 A: 2

    // stage registers
    float4 aA0, aB0, aA1, aB1;
    uint4  aL1, aL2;
    uint4  bL1, bL2;

    // ---- load stage for k0 ----
#define LOAD_STAGE(k0)                                                        \
    do {                                                                      \
        if (AHALF) {                                                          \
            const __half* Ah = (const __half*)Av +                            \
                (size_t)(m0 + hr) * K + (k0) + hg * 16;                       \
            aL1 = *(const uint4*)Ah; aL2 = *(const uint4*)(Ah + 8);           \
        } else {                                                              \
            const float* Af = (const float*)Av +                              \
                (size_t)(m0 + fr) * K + (k0) + fg * 16 + fq * 4;              \
            aA0 = *(const float4*)Af; aB0 = *(const float4*)(Af + 8);         \
            const float* Ag = Af + (size_t)64 * K;                            \
            aA1 = *(const float4*)Ag; aB1 = *(const float4*)(Ag + 8);         \
        }                                                                     \
        const __half* Bp = Wh + (size_t)(n0 + hr) * K + (k0) + hg * 16;       \
        bL1 = *(const uint4*)Bp; bL2 = *(const uint4*)(Bp + 8);               \
    } while (0)

#define STORE_STAGE(buf)                                                      \
    do {                                                                      \
        if (AHALF) {                                                          \
            unsigned* p = &As[buf][hr * AST + hg * 8];                        \
            *(uint2*)(p + 0) = make_uint2(aL1.x, aL2.x);                      \
            *(uint2*)(p + 2) = make_uint2(aL1.y, aL2.y);                      \
            *(uint2*)(p + 4) = make_uint2(aL1.z, aL2.z);                      \
            *(uint2*)(p + 6) = make_uint2(aL1.w, aL2.w);                      \
        } else {                                                              \
            *(uint4*)&As[buf][fr * AST + fg * 8 + fq * 4] =                   \
                make_uint4(packh2(aA0.x, aA0.y), packh2(aB0.x, aB0.y),        \
                           packh2(aA0.z, aA0.w), packh2(aB0.z, aB0.w));       \
            *(uint4*)&As[buf][(fr + 64) * AST + fg * 8 + fq * 4] =            \
                make_uint4(packh2(aA1.x, aA1.y), packh2(aB1.x, aB1.y),        \
                           packh2(aA1.z, aA1.w), packh2(aB1.z, aB1.w));       \
        }                                                                     \
        unsigned* bp = &Bs[buf][hr * AST + hg * 8];                           \
        *(uint2*)(bp + 0) = make_uint2(bL1.x, bL2.x);                         \
        *(uint2*)(bp + 2) = make_uint2(bL1.y, bL2.y);                         \
        *(uint2*)(bp + 4) = make_uint2(bL1.z, bL2.z);                         \
        *(uint2*)(bp + 6) = make_uint2(bL1.w, bL2.w);                         \
    } while (0)

    LOAD_STAGE(0);
    STORE_STAGE(0);
    __syncthreads();

    float acc[2][8][4] = {};

    for (int ks = 0; ks < KS; ks++) {
        const int nxt = ks + 1;
        if (nxt < KS) LOAD_STAGE(nxt << 5);

        const unsigned* Ab = As[ks & 1];
        const unsigned* Bb = Bs[ks & 1];
#pragma unroll
        for (int k16 = 0; k16 < 2; k16++) {
            unsigned af[2][4];
#pragma unroll
            for (int mf = 0; mf < 2; mf++) {
                const unsigned* ap =
                    &Ab[(wm * 32 + mf * 16 + qr) * AST + k16 * 8 + 2 * qc];
                uint2 lo = *(const uint2*)ap;
                uint2 hi = *(const uint2*)(ap + 8 * AST);
                af[mf][0] = lo.x; af[mf][1] = hi.x;
                af[mf][2] = lo.y; af[mf][3] = hi.y;
            }
#pragma unroll
            for (int nf = 0; nf < 8; nf++) {
                uint2 bb = *(const uint2*)
                    &Bb[(wn * 64 + nf * 8 + qr) * AST + k16 * 8 + 2 * qc];
                mma_f16(acc[0][nf], af[0], bb.x, bb.y);
                mma_f16(acc[1][nf], af[1], bb.x, bb.y);
            }
        }
        if (nxt < KS) {
            __syncthreads();
            STORE_STAGE(nxt & 1);
            __syncthreads();
        }
    }

    // ---- epilogue ----
    const bool transp = (chalf && z == tindex);
#pragma unroll
    for (int mf = 0; mf < 2; mf++) {
#pragma unroll
        for (int nf = 0; nf < 8; nf++) {
            const int col = n0 + wn * 64 + nf * 8 + 2 * qc;
            const float b0 = bias[col], b1 = bias[col + 1];
#pragma unroll
            for (int rr = 0; rr < 2; rr++) {
                const int row = m0 + wm * 32 + mf * 16 + qr + rr * 8;
                float o0 = acc[mf][nf][rr * 2 + 0] + b0;
                float o1 = acc[mf][nf][rr * 2 + 1] + b1;
                if (!chalf) {
                    float* Cf = (float*)C;
                    if (resid) {
                        const float* rp = resid + (size_t)row * DD + col;
                        o0 += rp[0]; o1 += rp[1];
                    }
                    *(float2*)(Cf + (size_t)row * DD + col) =
                        make_float2(o0, o1);
                } else if (transp) {
                    __half* Ch = (__half*)C;
                    Ch[(size_t)col * MTOT + row]       = __float2half(o0);
                    Ch[(size_t)(col + 1) * MTOT + row] = __float2half(o1);
                } else {
                    __half* Ch = (__half*)C;
                    __half2 hv = __floats2half2_rn(o0, o1);
                    *(__half2*)(Ch + (size_t)row * DD + col) = hv;
                }
            }
        }
    }
#undef LOAD_STAGE
#undef STORE_STAGE
}

// ---------------------------------------------------------------------------
// fp16 flash attention. Block = (h, itile64, b), 128 threads / 4 warps,
// warp owns 16 i-rows. Pair-permuted half2 smem, stride QST=40 words.
// q,k: half [tok][512]; vt: half [512][MTOT]; out: half [tok][512].
// ---------------------------------------------------------------------------
#define QST 40

__global__ __launch_bounds__(128) void attn_h(
    const __half* __restrict__ q, const __half* __restrict__ k,
    const __half* __restrict__ vt, const float* __restrict__ edges,
    const float* __restrict__ ewl, __half* __restrict__ out)
{
    __shared__ unsigned Qs[64 * QST];
    __shared__ unsigned Ks[64 * QST];
    __shared__ unsigned Vs[64 * QST];
    __shared__ unsigned Ps[64 * QST];

    const int h = blockIdx.x, it = blockIdx.y, b = blockIdx.z;
    const int i0 = it << 6;
    const int tid = threadIdx.x;
    const int w = tid >> 5, lane = tid & 31;
    const int qr = lane >> 2, qc = lane & 3;

    const float ew0 = ewl[0 * HH + h], ew1 = ewl[1 * HH + h];
    const float ew2 = ewl[2 * HH + h], ew3 = ewl[3 * HH + h];

    // tile loader: 256 tasks (row 0..63, group 0..3), 2 per thread
#define LOAD_TILE(dst, src, rstride)                                          \
    do {                                                                      \
        _Pragma("unroll")                                                     \
        for (int i_ = 0; i_ < 2; i_++) {                                      \
            const int t_ = tid + i_ * 128;                                    \
            const int row_ = t_ >> 2, g_ = t_ & 3;                            \
            const __half* p_ = (src) + (size_t)row_ * (rstride) + g_ * 16;    \
            uint4 L1 = *(const uint4*)p_;                                     \
            uint4 L2 = *(const uint4*)(p_ + 8);                               \
            unsigned* d_ = (dst) + row_ * QST + g_ * 8;                       \
            *(uint2*)(d_ + 0) = make_uint2(L1.x, L2.x);                       \
            *(uint2*)(d_ + 2) = make_uint2(L1.y, L2.y);                       \
            *(uint2*)(d_ + 4) = make_uint2(L1.z, L2.z);                       \
            *(uint2*)(d_ + 6) = make_uint2(L1.w, L2.w);                       \
        }                                                                     \
    } while (0)

    const __half* qbase = q + (size_t)(b * NN + i0) * DD + h * HDIM;
    LOAD_TILE(Qs, qbase, DD);
    __syncthreads();

    unsigned qf[4][4];
#pragma unroll
    for (int g = 0; g < 4; g++) {
        const unsigned* qp = &Qs[(w * 16 + qr) * QST + g * 8 + 2 * qc];
        uint2 lo = *(const uint2*)qp;
        uint2 hi = *(const uint2*)(qp + 8 * QST);
        qf[g][0] = lo.x; qf[g][1] = hi.x;
        qf[g][2] = lo.y; qf[g][3] = hi.y;
    }

    float m0v = -1e30f, m1v = -1e30f, l0v = 0.f, l1v = 0.f;
    float of[8][4] = {};

    const __half* kbase = k + (size_t)(b * NN) * DD + h * HDIM;
    const __half* vtb = vt + (size_t)(h * HDIM) * MTOT + b * NN;
    const int gi = i0 + w * 16 + qr;
    const size_t erow0 = ((size_t)b * NN + gi) * NN;
    const size_t erow1 = ((size_t)b * NN + gi + 8) * NN;

    for (int j0 = 0; j0 < NN; j0 += 64) {
        __syncthreads();
        LOAD_TILE(Ks, kbase + (size_t)j0 * DD, DD);
        LOAD_TILE(Vs, vtb + j0, MTOT);
        __syncthreads();

        // ---- S = Q K^T * 0.125 + edges . ew ----
        float s[8][4];
        const int gc0 = j0 + (qc << 1);
        float4 e00 = *(const float4*)(edges + (erow0 + gc0) * EE);
        float4 e01 = *(const float4*)(edges + (erow0 + gc0 + 1) * EE);
        float4 e10 = *(const float4*)(edges + (erow1 + gc0) * EE);
        float4 e11 = *(const float4*)(edges + (erow1 + gc0 + 1) * EE);
#pragma unroll
        for (int n8 = 0; n8 < 8; n8++) {
            float sd[4] = {};
            const unsigned* kp = &Ks[(n8 * 8 + qr) * QST + 2 * qc];
#pragma unroll
            for (int g = 0; g < 4; g++) {
                uint2 bb = *(const uint2*)(kp + g * 8);
                mma_f16(sd, qf[g], bb.x, bb.y);
            }
            float4 f00 = e00, f01 = e01, f10 = e10, f11 = e11;
            if (n8 < 7) {
                const int gc = j0 + (n8 + 1) * 8 + (qc << 1);
                e00 = *(const float4*)(edges + (erow0 + gc) * EE);
                e01 = *(const float4*)(edges + (erow0 + gc + 1) * EE);
                e10 = *(const float4*)(edges + (erow1 + gc) * EE);
                e11 = *(const float4*)(edges + (erow1 + gc + 1) * EE);
            }
            s[n8][0] = sd[0] * 0.125f + f00.x * ew0 + f00.y * ew1 + f00.z * ew2 + f00.w * ew3;
            s[n8][1] = sd[1] * 0.125f + f01.x * ew0 + f01.y * ew1 + f01.z * ew2 + f01.w * ew3;
            s[n8][2] = sd[2] * 0.125f + f10.x * ew0 + f10.y * ew1 + f10.z * ew2 + f10.w * ew3;
            s[n8][3] = sd[3] * 0.125f + f11.x * ew0 + f11.y * ew1 + f11.z * ew2 + f11.w * ew3;
        }

        // ---- online softmax ----
        float mt0 = -1e30f, mt1 = -1e30f;
#pragma unroll
        for (int n8 = 0; n8 < 8; n8++) {
            mt0 = fmaxf(mt0, fmaxf(s[n8][0], s[n8][1]));
            mt1 = fmaxf(mt1, fmaxf(s[n8][2], s[n8][3]));
        }
        mt0 = fmaxf(mt0, __shfl_xor_sync(0xffffffffu, mt0, 1));
        mt0 = fmaxf(mt0, __shfl_xor_sync(0xffffffffu, mt0, 2));
        mt1 = fmaxf(mt1, __shfl_xor_sync(0xffffffffu, mt1, 1));
        mt1 = fmaxf(mt1, __shfl_xor_sync(0xffffffffu, mt1, 2));
        const float mn0 = fmaxf(m0v, mt0), mn1 = fmaxf(m1v, mt1);
        const float f0 = __expf(m0v - mn0), f1 = __expf(m1v - mn1);
        m0v = mn0; m1v = mn1;

        float rs0 = 0.f, rs1 = 0.f;
#pragma unroll
        for (int n8 = 0; n8 < 8; n8++) {
            s[n8][0] = __expf(s[n8][0] - mn0);
            s[n8][1] = __expf(s[n8][1] - mn0);
            s[n8][2] = __expf(s[n8][2] - mn1);
            s[n8][3] = __expf(s[n8][3] - mn1);
            rs0 += s[n8][0] + s[n8][1];
            rs1 += s[n8][2] + s[n8][3];
        }
        rs0 += __shfl_xor_sync(0xffffffffu, rs0, 1);
        rs0 += __shfl_xor_sync(0xffffffffu, rs0, 2);
        rs1 += __shfl_xor_sync(0xffffffffu, rs1, 1);
        rs1 += __shfl_xor_sync(0xffffffffu, rs1, 2);
        l0v = l0v * f0 + rs0;
        l1v = l1v * f1 + rs1;

#pragma unroll
        for (int n8 = 0; n8 < 8; n8++) {
            of[n8][0] *= f0; of[n8][1] *= f0;
            of[n8][2] *= f1; of[n8][3] *= f1;
        }

        // ---- stash P as pair-permuted half2 (warp-private rows) ----
#pragma unroll
        for (int n8 = 0; n8 < 8; n8++) {
            const int base0 = (w * 16 + qr) * QST + (n8 >> 1) * 8 +
                              2 * qc + (n8 & 1);
            Ps[base0]            = packh2(s[n8][0], s[n8][1]);
            Ps[base0 + 8 * QST]  = packh2(s[n8][2], s[n8][3]);
        }
        __syncwarp();

        // ---- O += P @ V ----
#pragma unroll
        for (int g = 0; g < 4; g++) {
            const unsigned* pp = &Ps[(w * 16 + qr) * QST + g * 8 + 2 * qc];
            uint2 lo = *(const uint2*)pp;
            uint2 hi = *(const uint2*)(pp + 8 * QST);
            unsigned af[4] = {lo.x, hi.x, lo.y, hi.y};
#pragma unroll
            for (int n8 = 0; n8 < 8; n8++) {
                uint2 vv = *(const uint2*)
                    &Vs[(n8 * 8 + qr) * QST + g * 8 + 2 * qc];
                mma_f16(of[n8], af, vv.x, vv.y);
            }
        }
        __syncwarp();
    }

    // ---- epilogue ----
    __half* obase = out + (size_t)(b * NN + i0 + w * 16 + qr) * DD + h * HDIM;
    const float inv0 = 1.0f / l0v, inv1 = 1.0f / l1v;
#pragma unroll
    for (int n8 = 0; n8 < 8; n8++) {
        const int col = n8 * 8 + (qc << 1);
        *(__half2*)(obase + col) =
            __floats2half2_rn(of[n8][0] * inv0, of[n8][1] * inv0);
        *(__half2*)(obase + (size_t)8 * DD + col) =
            __floats2half2_rn(of[n8][2] * inv1, of[n8][3] * inv1);
    }
#undef LOAD_TILE
}

// ---------------------------------------------------------------------------
// Row LayerNorm
// ---------------------------------------------------------------------------
__device__ __forceinline__ float warp_sum(float s) {
#pragma unroll
    for (int o = 16; o; o >>= 1) s += __shfl_xor_sync(0xffffffffu, s, o);
    return s;
}

__global__ __launch_bounds__(128) void ln_kernel(
    const float* __restrict__ hin, const float* __restrict__ gw,
    const float* __restrict__ gb, float* __restrict__ out)
{
    __shared__ float red[4];
    const int row = blockIdx.x;
    const int tid = threadIdx.x;
    const int wid = tid >> 5, lane = tid & 31;
    const float* hr = hin + (size_t)row * DD;

    float4 x = *(const float4*)(hr + (tid << 2));
    float s = x.x + x.y + x.z + x.w;
    s = warp_sum(s);
    if (lane == 0) red[wid] = s;
    __syncthreads();
    float mu = (red[0] + red[1] + red[2] + red[3]) * (1.0f / DD);
    __syncthreads();

    float d0 = x.x - mu, d1 = x.y - mu, d2 = x.z - mu, d3 = x.w - mu;
    float vs = d0 * d0 + d1 * d1 + d2 * d2 + d3 * d3;
    vs = warp_sum(vs);
    if (lane == 0) red[wid] = vs;
    __syncthreads();
    float var = (red[0] + red[1] + red[2] + red[3]) * (1.0f / DD);
    float inv = rsqrtf(var + 1e-5f);

    float4 g4 = *(const float4*)(gw + (tid << 2));
    float4 b4 = *(const float4*)(gb + (tid << 2));
    float4 o;
    o.x = d0 * inv * g4.x + b4.x;
    o.y = d1 * inv * g4.y + b4.y;
    o.z = d2 * inv * g4.z + b4.z;
    o.w = d3 * inv * g4.w + b4.w;
    *(float4*)(out + (size_t)row * DD + (tid << 2)) = o;
}

// ---------------------------------------------------------------------------
// Host launcher
// ---------------------------------------------------------------------------
extern "C" void kernel_launch(void* const* d_in, const int* in_sizes, int n_in,
                              void* d_out, int out_size)
{
    const float* x     = (const float*)d_in[0];
    const float* edges = (const float*)d_in[1];
    const float* in_w  = (const float*)d_in[2];
    const float* in_b  = (const float*)d_in[3];
    const float* qw    = (const float*)d_in[4];
    const float* qb    = (const float*)d_in[5];
    const float* kw    = (const float*)d_in[6];
    const float* kb    = (const float*)d_in[7];
    const float* vw    = (const float*)d_in[8];
    const float* vb    = (const float*)d_in[9];
    const float* ow    = (const float*)d_in[10];
    const float* ob    = (const float*)d_in[11];
    const float* ew    = (const float*)d_in[12];
    // d_in[13] = eb: constant over j, cancels in softmax -> unused
    const float* ln_g  = (const float*)d_in[14];
    const float* ln_b  = (const float*)d_in[15];

    void* sp = nullptr;
    cudaGetSymbolAddress(&sp, g_scratch);
    unsigned char* base = (unsigned char*)sp;
    float*  h    = (float*)base;                          // 8 MB
    __half* qh   = (__half*)(base + 8388608);
    __half* kh   = qh  + (size_t)MTOT * DD;
    __half* vth  = kh  + (size_t)MTOT * DD;
    __half* atth = vth + (size_t)MTOT * DD;
    __half* wh_in = atth + (size_t)MTOT * DD;             // [512][128]
    __half* wh_q  = wh_in + 512 * 128;                    // [3][512][512]
    __half* wh_k  = wh_q + 3 * 512 * 512;
    __half* wh_v  = wh_k + 3 * 512 * 512;
    __half* wh_o  = wh_v + 3 * 512 * 512;

    // one-time (per launch) weight transposes to half [n][k]
    transpose_w<<<dim3(16, 4, 1), 256>>>(in_w, wh_in, 128, 512);
    transpose_w<<<dim3(16, 16, 3), 256>>>(qw, wh_q, 512, 512);
    transpose_w<<<dim3(16, 16, 3), 256>>>(kw, wh_k, 512, 512);
    transpose_w<<<dim3(16, 16, 3), 256>>>(vw, wh_v, 512, 512);
    transpose_w<<<dim3(16, 16, 3), 256>>>(ow, wh_o, 512, 512);

    dim3 gg(4, 32, 1);   // 128 CTAs
    dim3 g3(4, 32, 3);
    dim3 ga(HH, NN / 64, BB);

    // h = x @ in_w + in_b   (A fp32, C fp32)
    gemm_h<0><<<gg, 256>>>(x, wh_in, wh_in, wh_in, in_b, in_b, in_b,
                           h, h, h, nullptr, 128, 0, -1);

    for (int l = 0; l < LL; l++) {
        const __half* whq = wh_q + (size_t)l * 512 * 512;
        const __half* whk = wh_k + (size_t)l * 512 * 512;
        const __half* whv = wh_v + (size_t)l * 512 * 512;
        const __half* who = wh_o + (size_t)l * 512 * 512;
        const float* qbl = qb + (size_t)l * DD;
        const float* kbl = kb + (size_t)l * DD;
        const float* vbl = vb + (size_t)l * DD;
        const float* obl = ob + (size_t)l * DD;
        const float* ewl = ew + (size_t)l * EE * HH;

        // fused QKV (A fp32 h, C half; z=2 -> v transposed)
        gemm_h<0><<<g3, 256>>>(h, whq, whk, whv, qbl, kbl, vbl,
                               qh, kh, vth, nullptr, 512, 1, 2);

        attn_h<<<ga, 128>>>(qh, kh, vth, edges, ewl, atth);

        // h = h + att @ ow + ob   (A half, C fp32 + resid)
        gemm_h<1><<<gg, 256>>>(atth, who, who, who, obl, obl, obl,
                               h, h, h, h, 512, 0, -1);
    }

    ln_kernel<<<MTOT, 128>>>(h, ln_g, ln_b, (float*)d_out);
}

// round 5
// speedup vs baseline: 4.1285x; 1.3549x over previous
#include <cuda_runtime.h>
#include <cuda_fp16.h>
#include <math.h>

// Problem constants
#define BB    4
#define NN    1024
#define DD    512
#define HH    8
#define HDIM  64
#define EE    4
#define LL    3
#define MTOT  (BB*NN)   // 4096

// Scratch: h fp32 | q,k,vt,att half | weights half | edge-bias half (67MB)
__device__ __align__(256) unsigned char g_scratch[98697216];

// ---------------------------------------------------------------------------
// Helpers
// ---------------------------------------------------------------------------
__device__ __forceinline__ unsigned packh2(float lo, float hi) {
    __half2 h = __floats2half2_rn(lo, hi);
    return *reinterpret_cast<unsigned*>(&h);
}

__device__ __forceinline__ void mma_f16(float c[4], const unsigned a[4],
                                        unsigned b0, unsigned b1) {
    asm volatile(
        "mma.sync.aligned.m16n8k16.row.col.f32.f16.f16.f32 "
        "{%0,%1,%2,%3}, {%4,%5,%6,%7}, {%8,%9}, {%0,%1,%2,%3};\n"
        : "+f"(c[0]), "+f"(c[1]), "+f"(c[2]), "+f"(c[3])
        : "r"(a[0]), "r"(a[1]), "r"(a[2]), "r"(a[3]), "r"(b0), "r"(b1));
}

// ---------------------------------------------------------------------------
// Weight transpose + fp16 convert: dst[n][k] = (half)src[k][n], 32x32 tiles
// ---------------------------------------------------------------------------
__device__ __forceinline__ void transpose_body(
    const float* __restrict__ src, __half* __restrict__ dst, int K, int N)
{
    __shared__ float t[32][33];
    const int k0 = blockIdx.y * 32, n0 = blockIdx.x * 32;
    const int c = threadIdx.x & 31, r0 = threadIdx.x >> 5;
#pragma unroll
    for (int i = 0; i < 4; i++) {
        int r = r0 + i * 8;
        t[r][c] = src[(size_t)(k0 + r) * N + n0 + c];
    }
    __syncthreads();
#pragma unroll
    for (int i = 0; i < 4; i++) {
        int r = r0 + i * 8;
        dst[(size_t)(n0 + r) * K + k0 + c] = __float2half(t[c][r]);
    }
}

__global__ void transpose_w(const float* __restrict__ src,
                            __half* __restrict__ dst, int K, int N)
{
    transpose_body(src, dst, K, N);
}

// z = 0..11: group g = z/3 picks weight set, l = z%3 picks layer slice
__global__ void transpose_w4(
    const float* __restrict__ sq, const float* __restrict__ sk,
    const float* __restrict__ sv, const float* __restrict__ so,
    __half* __restrict__ dq, __half* __restrict__ dk,
    __half* __restrict__ dv, __half* __restrict__ dw)
{
    const int z = blockIdx.z, g = z / 3, l = z % 3;
    const size_t off = (size_t)l * DD * DD;
    const float* src = ((g == 0) ? sq : (g == 1) ? sk : (g == 2) ? sv : so) + off;
    __half* dst = ((g == 0) ? dq : (g == 1) ? dk : (g == 2) ? dv : dw) + off;
    transpose_body(src, dst, DD, DD);
}

// ---------------------------------------------------------------------------
// Edge bias precompute (per layer): eb[(b*HH+h)][i][j] = edges[b,i,j,:].ew[:,h]
// grid (NN, BB), 256 threads, 4 j per thread.
// ---------------------------------------------------------------------------
__global__ __launch_bounds__(256) void edgebias_h(
    const float* __restrict__ edges, const float* __restrict__ ewl,
    __half* __restrict__ eb)
{
    __shared__ float sew[EE * HH];
    const int tid = threadIdx.x;
    if (tid < EE * HH) sew[tid] = ewl[tid];
    __syncthreads();
    const int i = blockIdx.x, b = blockIdx.y;
    const int j0 = tid << 2;
    const float* ep = edges + (((size_t)b * NN + i) * NN + j0) * EE;
    float4 e[4];
#pragma unroll
    for (int t = 0; t < 4; t++) e[t] = *(const float4*)(ep + t * EE);
#pragma unroll
    for (int hh = 0; hh < HH; hh++) {
        const float w0 = sew[0 * HH + hh], w1 = sew[1 * HH + hh];
        const float w2 = sew[2 * HH + hh], w3 = sew[3 * HH + hh];
        float bv[4];
#pragma unroll
        for (int t = 0; t < 4; t++)
            bv[t] = e[t].x * w0 + e[t].y * w1 + e[t].z * w2 + e[t].w * w3;
        __half* dst = eb + (((size_t)(b * HH + hh)) * NN + i) * NN + j0;
        *(uint2*)dst = make_uint2(packh2(bv[0], bv[1]), packh2(bv[2], bv[3]));
    }
}

// ---------------------------------------------------------------------------
// fp16 GEMM: C[M,512] = A[M,K] @ Wh^T + bias (+resid), optional scale.
// BM=128 BN=128 BK=32, 8 warps (4m x 2n), warp tile 32x64.
// Pair-permuted smem (LDS.64 fragments), stride AST=24.
// ---------------------------------------------------------------------------
#define AST 24
#define TWORDS (128*AST)

template<int AHALF>
__global__ __launch_bounds__(256, 2) void gemm_h(
    const void* __restrict__ Av,
    const __half* __restrict__ Wh0, const __half* __restrict__ Wh1,
    const __half* __restrict__ Wh2,
    const float* __restrict__ bs0, const float* __restrict__ bs1,
    const float* __restrict__ bs2,
    void* __restrict__ C0, void* __restrict__ C1, void* __restrict__ C2,
    const float* __restrict__ resid, int K, int chalf, int tindex,
    float scl0)
{
    __shared__ unsigned As[2][TWORDS];
    __shared__ unsigned Bs[2][TWORDS];

    const int z = blockIdx.z;
    const __half* Wh   = (z == 0) ? Wh0 : (z == 1) ? Wh1 : Wh2;
    const float*  bias = (z == 0) ? bs0 : (z == 1) ? bs1 : bs2;
    void*         C    = (z == 0) ? C0  : (z == 1) ? C1  : C2;
    const float   sc   = (z == 0) ? scl0 : 1.0f;

    const int tid = threadIdx.x;
    const int wid = tid >> 5, lane = tid & 31;
    const int wm = wid & 3, wn = wid >> 2;
    const int qr = lane >> 2, qc = lane & 3;
    const int m0 = blockIdx.y * 128, n0 = blockIdx.x * 128;
    const int KS = K >> 5;

    const int hr = tid >> 1, hg = tid & 1;
    const int fr = tid >> 2, fg = (tid >> 1) & 1, fq = tid & 1;

    float4 aA0, aB0, aA1, aB1;
    uint4  aL1, aL2;
    uint4  bL1, bL2;

#define LOAD_STAGE(k0)                                                        \
    do {                                                                      \
        if (AHALF) {                                                          \
            const __half* Ah = (const __half*)Av +                            \
                (size_t)(m0 + hr) * K + (k0) + hg * 16;                       \
            aL1 = *(const uint4*)Ah; aL2 = *(const uint4*)(Ah + 8);           \
        } else {                                                              \
            const float* Af = (const float*)Av +                              \
                (size_t)(m0 + fr) * K + (k0) + fg * 16 + fq * 4;              \
            aA0 = *(const float4*)Af; aB0 = *(const float4*)(Af + 8);         \
            const float* Ag = Af + (size_t)64 * K;                            \
            aA1 = *(const float4*)Ag; aB1 = *(const float4*)(Ag + 8);         \
        }                                                                     \
        const __half* Bp = Wh + (size_t)(n0 + hr) * K + (k0) + hg * 16;       \
        bL1 = *(const uint4*)Bp; bL2 = *(const uint4*)(Bp + 8);               \
    } while (0)

#define STORE_STAGE(buf)                                                      \
    do {                                                                      \
        if (AHALF) {                                                          \
            unsigned* p = &As[buf][hr * AST + hg * 8];                        \
            *(uint2*)(p + 0) = make_uint2(aL1.x, aL2.x);                      \
            *(uint2*)(p + 2) = make_uint2(aL1.y, aL2.y);                      \
            *(uint2*)(p + 4) = make_uint2(aL1.z, aL2.z);                      \
            *(uint2*)(p + 6) = make_uint2(aL1.w, aL2.w);                      \
        } else {                                                              \
            *(uint4*)&As[buf][fr * AST + fg * 8 + fq * 4] =                   \
                make_uint4(packh2(aA0.x, aA0.y), packh2(aB0.x, aB0.y),        \
                           packh2(aA0.z, aA0.w), packh2(aB0.z, aB0.w));       \
            *(uint4*)&As[buf][(fr + 64) * AST + fg * 8 + fq * 4] =            \
                make_uint4(packh2(aA1.x, aA1.y), packh2(aB1.x, aB1.y),        \
                           packh2(aA1.z, aA1.w), packh2(aB1.z, aB1.w));       \
        }                                                                     \
        unsigned* bp = &Bs[buf][hr * AST + hg * 8];                           \
        *(uint2*)(bp + 0) = make_uint2(bL1.x, bL2.x);                         \
        *(uint2*)(bp + 2) = make_uint2(bL1.y, bL2.y);                         \
        *(uint2*)(bp + 4) = make_uint2(bL1.z, bL2.z);                         \
        *(uint2*)(bp + 6) = make_uint2(bL1.w, bL2.w);                         \
    } while (0)

    LOAD_STAGE(0);
    STORE_STAGE(0);
    __syncthreads();

    float acc[2][8][4] = {};

    for (int ks = 0; ks < KS; ks++) {
        const int nxt = ks + 1;
        if (nxt < KS) LOAD_STAGE(nxt << 5);

        const unsigned* Ab = As[ks & 1];
        const unsigned* Bb = Bs[ks & 1];
#pragma unroll
        for (int k16 = 0; k16 < 2; k16++) {
            unsigned af[2][4];
#pragma unroll
            for (int mf = 0; mf < 2; mf++) {
                const unsigned* ap =
                    &Ab[(wm * 32 + mf * 16 + qr) * AST + k16 * 8 + 2 * qc];
                uint2 lo = *(const uint2*)ap;
                uint2 hi = *(const uint2*)(ap + 8 * AST);
                af[mf][0] = lo.x; af[mf][1] = hi.x;
                af[mf][2] = lo.y; af[mf][3] = hi.y;
            }
#pragma unroll
            for (int nf = 0; nf < 8; nf++) {
                uint2 bb = *(const uint2*)
                    &Bb[(wn * 64 + nf * 8 + qr) * AST + k16 * 8 + 2 * qc];
                mma_f16(acc[0][nf], af[0], bb.x, bb.y);
                mma_f16(acc[1][nf], af[1], bb.x, bb.y);
            }
        }
        if (nxt < KS) {
            __syncthreads();
            STORE_STAGE(nxt & 1);
            __syncthreads();
        }
    }

    const bool transp = (chalf && z == tindex);
#pragma unroll
    for (int mf = 0; mf < 2; mf++) {
#pragma unroll
        for (int nf = 0; nf < 8; nf++) {
            const int col = n0 + wn * 64 + nf * 8 + 2 * qc;
            const float b0 = bias[col], b1 = bias[col + 1];
#pragma unroll
            for (int rr = 0; rr < 2; rr++) {
                const int row = m0 + wm * 32 + mf * 16 + qr + rr * 8;
                float o0 = (acc[mf][nf][rr * 2 + 0] + b0) * sc;
                float o1 = (acc[mf][nf][rr * 2 + 1] + b1) * sc;
                if (!chalf) {
                    float* Cf = (float*)C;
                    if (resid) {
                        const float* rp = resid + (size_t)row * DD + col;
                        o0 += rp[0]; o1 += rp[1];
                    }
                    *(float2*)(Cf + (size_t)row * DD + col) =
                        make_float2(o0, o1);
                } else if (transp) {
                    __half* Ch = (__half*)C;
                    Ch[(size_t)col * MTOT + row]       = __float2half(o0);
                    Ch[(size_t)(col + 1) * MTOT + row] = __float2half(o1);
                } else {
                    __half* Ch = (__half*)C;
                    __half2 hv = __floats2half2_rn(o0, o1);
                    *(__half2*)(Ch + (size_t)row * DD + col) = hv;
                }
            }
        }
    }
#undef LOAD_STAGE
#undef STORE_STAGE
}

// ---------------------------------------------------------------------------
// fp16 flash attention with precomputed fp16 edge bias.
// Block = (h, itile64, b), 128 threads / 4 warps, warp = 16 i-rows.
// q pre-scaled by 0.125 in projection. eb planes indexed (b*HH+h).
// ---------------------------------------------------------------------------
#define QST 40

__global__ __launch_bounds__(128) void attn_h(
    const __half* __restrict__ q, const __half* __restrict__ k,
    const __half* __restrict__ vt, const __half* __restrict__ eb,
    __half* __restrict__ out)
{
    __shared__ unsigned Qs[64 * QST];
    __shared__ unsigned Ks[64 * QST];
    __shared__ unsigned Vs[64 * QST];
    __shared__ unsigned Ps[64 * QST];

    const int h = blockIdx.x, it = blockIdx.y, b = blockIdx.z;
    const int i0 = it << 6;
    const int tid = threadIdx.x;
    const int w = tid >> 5, lane = tid & 31;
    const int qr = lane >> 2, qc = lane & 3;

#define LOAD_TILE(dst, src, rstride)                                          \
    do {                                                                      \
        _Pragma("unroll")                                                     \
        for (int i_ = 0; i_ < 2; i_++) {                                      \
            const int t_ = tid + i_ * 128;                                    \
            const int row_ = t_ >> 2, g_ = t_ & 3;                            \
            const __half* p_ = (src) + (size_t)row_ * (rstride) + g_ * 16;    \
            uint4 L1 = *(const uint4*)p_;                                     \
            uint4 L2 = *(const uint4*)(p_ + 8);                               \
            unsigned* d_ = (dst) + row_ * QST + g_ * 8;                       \
            *(uint2*)(d_ + 0) = make_uint2(L1.x, L2.x);                       \
            *(uint2*)(d_ + 2) = make_uint2(L1.y, L2.y);                       \
            *(uint2*)(d_ + 4) = make_uint2(L1.z, L2.z);                       \
            *(uint2*)(d_ + 6) = make_uint2(L1.w, L2.w);                       \
        }                                                                     \
    } while (0)

    const __half* qbase = q + (size_t)(b * NN + i0) * DD + h * HDIM;
    LOAD_TILE(Qs, qbase, DD);
    __syncthreads();

    unsigned qf[4][4];
#pragma unroll
    for (int g = 0; g < 4; g++) {
        const unsigned* qp = &Qs[(w * 16 + qr) * QST + g * 8 + 2 * qc];
        uint2 lo = *(const uint2*)qp;
        uint2 hi = *(const uint2*)(qp + 8 * QST);
        qf[g][0] = lo.x; qf[g][1] = hi.x;
        qf[g][2] = lo.y; qf[g][3] = hi.y;
    }

    float m0v = -1e30f, m1v = -1e30f, l0v = 0.f, l1v = 0.f;
    float of[8][4] = {};

    const __half* kbase = k + (size_t)(b * NN) * DD + h * HDIM;
    const __half* vtb = vt + (size_t)(h * HDIM) * MTOT + b * NN;
    const int gi = i0 + w * 16 + qr;
    const __half* bp0 = eb + ((size_t)(b * HH + h) * NN + gi) * NN + 2 * qc;
    const __half* bp1 = bp0 + (size_t)8 * NN;

    for (int j0 = 0; j0 < NN; j0 += 64) {
        __syncthreads();
        LOAD_TILE(Ks, kbase + (size_t)j0 * DD, DD);
        LOAD_TILE(Vs, vtb + j0, MTOT);
        __syncthreads();

        // bias prefetch (overlaps with the S mma chain)
        __half2 Bv0[8], Bv1[8];
#pragma unroll
        for (int n8 = 0; n8 < 8; n8++) {
            Bv0[n8] = *(const __half2*)(bp0 + j0 + n8 * 8);
            Bv1[n8] = *(const __half2*)(bp1 + j0 + n8 * 8);
        }

        // ---- S = Q K^T (q pre-scaled) + bias ----
        float s[8][4];
#pragma unroll
        for (int n8 = 0; n8 < 8; n8++) {
            float sd[4] = {};
            const unsigned* kp = &Ks[(n8 * 8 + qr) * QST + 2 * qc];
#pragma unroll
            for (int g = 0; g < 4; g++) {
                uint2 bb = *(const uint2*)(kp + g * 8);
                mma_f16(sd, qf[g], bb.x, bb.y);
            }
            float2 f0 = __half22float2(Bv0[n8]);
            float2 f1 = __half22float2(Bv1[n8]);
            s[n8][0] = sd[0] + f0.x;
            s[n8][1] = sd[1] + f0.y;
            s[n8][2] = sd[2] + f1.x;
            s[n8][3] = sd[3] + f1.y;
        }

        // ---- online softmax ----
        float mt0 = -1e30f, mt1 = -1e30f;
#pragma unroll
        for (int n8 = 0; n8 < 8; n8++) {
            mt0 = fmaxf(mt0, fmaxf(s[n8][0], s[n8][1]));
            mt1 = fmaxf(mt1, fmaxf(s[n8][2], s[n8][3]));
        }
        mt0 = fmaxf(mt0, __shfl_xor_sync(0xffffffffu, mt0, 1));
        mt0 = fmaxf(mt0, __shfl_xor_sync(0xffffffffu, mt0, 2));
        mt1 = fmaxf(mt1, __shfl_xor_sync(0xffffffffu, mt1, 1));
        mt1 = fmaxf(mt1, __shfl_xor_sync(0xffffffffu, mt1, 2));
        const float mn0 = fmaxf(m0v, mt0), mn1 = fmaxf(m1v, mt1);
        const float f0 = __expf(m0v - mn0), f1 = __expf(m1v - mn1);
        m0v = mn0; m1v = mn1;

        float rs0 = 0.f, rs1 = 0.f;
#pragma unroll
        for (int n8 = 0; n8 < 8; n8++) {
            s[n8][0] = __expf(s[n8][0] - mn0);
            s[n8][1] = __expf(s[n8][1] - mn0);
            s[n8][2] = __expf(s[n8][2] - mn1);
            s[n8][3] = __expf(s[n8][3] - mn1);
            rs0 += s[n8][0] + s[n8][1];
            rs1 += s[n8][2] + s[n8][3];
        }
        rs0 += __shfl_xor_sync(0xffffffffu, rs0, 1);
        rs0 += __shfl_xor_sync(0xffffffffu, rs0, 2);
        rs1 += __shfl_xor_sync(0xffffffffu, rs1, 1);
        rs1 += __shfl_xor_sync(0xffffffffu, rs1, 2);
        l0v = l0v * f0 + rs0;
        l1v = l1v * f1 + rs1;

#pragma unroll
        for (int n8 = 0; n8 < 8; n8++) {
            of[n8][0] *= f0; of[n8][1] *= f0;
            of[n8][2] *= f1; of[n8][3] *= f1;
        }

        // ---- stash P as pair-permuted half2 ----
#pragma unroll
        for (int n8 = 0; n8 < 8; n8++) {
            const int base0 = (w * 16 + qr) * QST + (n8 >> 1) * 8 +
                              2 * qc + (n8 & 1);
            Ps[base0]           = packh2(s[n8][0], s[n8][1]);
            Ps[base0 + 8 * QST] = packh2(s[n8][2], s[n8][3]);
        }
        __syncwarp();

        // ---- O += P @ V ----
#pragma unroll
        for (int g = 0; g < 4; g++) {
            const unsigned* pp = &Ps[(w * 16 + qr) * QST + g * 8 + 2 * qc];
            uint2 lo = *(const uint2*)pp;
            uint2 hi = *(const uint2*)(pp + 8 * QST);
            unsigned af[4] = {lo.x, hi.x, lo.y, hi.y};
#pragma unroll
            for (int n8 = 0; n8 < 8; n8++) {
                uint2 vv = *(const uint2*)
                    &Vs[(n8 * 8 + qr) * QST + g * 8 + 2 * qc];
                mma_f16(of[n8], af, vv.x, vv.y);
            }
        }
        __syncwarp();
    }

    __half* obase = out + (size_t)(b * NN + i0 + w * 16 + qr) * DD + h * HDIM;
    const float inv0 = 1.0f / l0v, inv1 = 1.0f / l1v;
#pragma unroll
    for (int n8 = 0; n8 < 8; n8++) {
        const int col = n8 * 8 + (qc << 1);
        *(__half2*)(obase + col) =
            __floats2half2_rn(of[n8][0] * inv0, of[n8][1] * inv0);
        *(__half2*)(obase + (size_t)8 * DD + col) =
            __floats2half2_rn(of[n8][2] * inv1, of[n8][3] * inv1);
    }
#undef LOAD_TILE
}

// ---------------------------------------------------------------------------
// Row LayerNorm
// ---------------------------------------------------------------------------
__device__ __forceinline__ float warp_sum(float s) {
#pragma unroll
    for (int o = 16; o; o >>= 1) s += __shfl_xor_sync(0xffffffffu, s, o);
    return s;
}

__global__ __launch_bounds__(128) void ln_kernel(
    const float* __restrict__ hin, const float* __restrict__ gw,
    const float* __restrict__ gb, float* __restrict__ out)
{
    __shared__ float red[4];
    const int row = blockIdx.x;
    const int tid = threadIdx.x;
    const int wid = tid >> 5, lane = tid & 31;
    const float* hr = hin + (size_t)row * DD;

    float4 x = *(const float4*)(hr + (tid << 2));
    float s = x.x + x.y + x.z + x.w;
    s = warp_sum(s);
    if (lane == 0) red[wid] = s;
    __syncthreads();
    float mu = (red[0] + red[1] + red[2] + red[3]) * (1.0f / DD);
    __syncthreads();

    float d0 = x.x - mu, d1 = x.y - mu, d2 = x.z - mu, d3 = x.w - mu;
    float vs = d0 * d0 + d1 * d1 + d2 * d2 + d3 * d3;
    vs = warp_sum(vs);
    if (lane == 0) red[wid] = vs;
    __syncthreads();
    float var = (red[0] + red[1] + red[2] + red[3]) * (1.0f / DD);
    float inv = rsqrtf(var + 1e-5f);

    float4 g4 = *(const float4*)(gw + (tid << 2));
    float4 b4 = *(const float4*)(gb + (tid << 2));
    float4 o;
    o.x = d0 * inv * g4.x + b4.x;
    o.y = d1 * inv * g4.y + b4.y;
    o.z = d2 * inv * g4.z + b4.z;
    o.w = d3 * inv * g4.w + b4.w;
    *(float4*)(out + (size_t)row * DD + (tid << 2)) = o;
}

// ---------------------------------------------------------------------------
// Host launcher
// ---------------------------------------------------------------------------
extern "C" void kernel_launch(void* const* d_in, const int* in_sizes, int n_in,
                              void* d_out, int out_size)
{
    const float* x     = (const float*)d_in[0];
    const float* edges = (const float*)d_in[1];
    const float* in_w  = (const float*)d_in[2];
    const float* in_b  = (const float*)d_in[3];
    const float* qw    = (const float*)d_in[4];
    const float* qb    = (const float*)d_in[5];
    const float* kw    = (const float*)d_in[6];
    const float* kb    = (const float*)d_in[7];
    const float* vw    = (const float*)d_in[8];
    const float* vb    = (const float*)d_in[9];
    const float* ow    = (const float*)d_in[10];
    const float* ob    = (const float*)d_in[11];
    const float* ew    = (const float*)d_in[12];
    // d_in[13] = eb: constant over j, cancels in softmax -> unused
    const float* ln_g  = (const float*)d_in[14];
    const float* ln_b  = (const float*)d_in[15];

    void* sp = nullptr;
    cudaGetSymbolAddress(&sp, g_scratch);
    unsigned char* base = (unsigned char*)sp;
    float*  h    = (float*)base;                          // 8 MB
    __half* qh   = (__half*)(base + 8388608);
    __half* kh   = qh  + (size_t)MTOT * DD;
    __half* vth  = kh  + (size_t)MTOT * DD;
    __half* atth = vth + (size_t)MTOT * DD;
    __half* wh_in = atth + (size_t)MTOT * DD;             // [512][128]
    __half* wh_q  = wh_in + 512 * 128;                    // [3][512][512]
    __half* wh_k  = wh_q + 3 * 512 * 512;
    __half* wh_v  = wh_k + 3 * 512 * 512;
    __half* wh_o  = wh_v + 3 * 512 * 512;
    __half* ebias = wh_o + 3 * 512 * 512;                 // [BB*HH][NN][NN]

    // weight transposes to half [n][k]
    transpose_w<<<dim3(16, 4, 1), 256>>>(in_w, wh_in, 128, 512);
    transpose_w4<<<dim3(16, 16, 12), 256>>>(qw, kw, vw, ow,
                                            wh_q, wh_k, wh_v, wh_o);

    dim3 gg(4, 32, 1);
    dim3 g3(4, 32, 3);
    dim3 ga(HH, NN / 64, BB);

    // h = x @ in_w + in_b
    gemm_h<0><<<gg, 256>>>(x, wh_in, wh_in, wh_in, in_b, in_b, in_b,
                           h, h, h, nullptr, 128, 0, -1, 1.0f);

    for (int l = 0; l < LL; l++) {
        const __half* whq = wh_q + (size_t)l * 512 * 512;
        const __half* whk = wh_k + (size_t)l * 512 * 512;
        const __half* whv = wh_v + (size_t)l * 512 * 512;
        const __half* who = wh_o + (size_t)l * 512 * 512;
        const float* qbl = qb + (size_t)l * DD;
        const float* kbl = kb + (size_t)l * DD;
        const float* vbl = vb + (size_t)l * DD;
        const float* obl = ob + (size_t)l * DD;
        const float* ewl = ew + (size_t)l * EE * HH;

        // per-layer fp16 edge bias
        edgebias_h<<<dim3(NN, BB), 256>>>(edges, ewl, ebias);

        // fused QKV; q pre-scaled by 1/sqrt(HD); v transposed
        gemm_h<0><<<g3, 256>>>(h, whq, whk, whv, qbl, kbl, vbl,
                               qh, kh, vth, nullptr, 512, 1, 2, 0.125f);

        attn_h<<<ga, 128>>>(qh, kh, vth, ebias, atth);

        // h = h + att @ ow + ob
        gemm_h<1><<<gg, 256>>>(atth, who, who, who, obl, obl, obl,
                               h, h, h, h, 512, 0, -1, 1.0f);
    }

    ln_kernel<<<MTOT, 128>>>(h, ln_g, ln_b, (float*)d_out);
}